// round 13
// baseline (speedup 1.0000x reference)
#include <cuda_runtime.h>
#include <cuda_bf16.h>
#include <math.h>
#include <stdint.h>

#define B_      2
#define S_      2048
#define HID_    2048
#define H_      16
#define QLORA_  1536
#define KVLORA_ 512
#define DR_     64
#define DN_     128
#define DQK_    192
#define DV_     128
#define NTOK_   (B_*S_)
#define SCALING_ 0.07216878364870322f
#define CSCALE_ 16.0f
#define CINV_   0.0625f

typedef __nv_bfloat16 bf16;

/* scratch: "h" = bf16(x), "p" = bf16(h + 16*(x-h)) */
__device__ bf16  g_hs_h [NTOK_*HID_];
__device__ bf16  g_hs_p [NTOK_*HID_];
__device__ float g_qlat  [NTOK_*QLORA_];
__device__ bf16  g_qlatn_h[NTOK_*QLORA_];
__device__ bf16  g_qlatn_p[NTOK_*QLORA_];
__device__ float g_qflat [NTOK_*H_*DQK_];
__device__ bf16  g_qfull_h[B_*H_*S_*DQK_];
__device__ bf16  g_qfull_p[B_*H_*S_*DQK_];
__device__ float g_ckv   [NTOK_*(KVLORA_+DR_)];
__device__ bf16  g_kc_h [NTOK_*KVLORA_];
__device__ bf16  g_kc_p [NTOK_*KVLORA_];
__device__ float g_kpe   [B_*S_*DR_];
__device__ float g_kvflat[NTOK_*H_*(DN_+DV_)];
__device__ bf16  g_kfull_h[B_*H_*S_*DQK_];
__device__ bf16  g_kfull_p[B_*H_*S_*DQK_];
__device__ bf16  g_vT_h [B_*H_*DV_*S_];
__device__ bf16  g_vT_p [B_*H_*DV_*S_];
__device__ bf16  g_w_h  [(long long)B_*H_*S_*S_];
__device__ bf16  g_w_p  [(long long)B_*H_*S_*S_];
__device__ bf16  g_omid_h[NTOK_*H_*DV_];
__device__ bf16  g_omid_p[NTOK_*H_*DV_];
__device__ bf16  g_wqaT_h [QLORA_*HID_];
__device__ bf16  g_wqaT_p [QLORA_*HID_];
__device__ bf16  g_wqbT_h [H_*DQK_*QLORA_];
__device__ bf16  g_wqbT_p [H_*DQK_*QLORA_];
__device__ bf16  g_wkvaT_h[(KVLORA_+DR_)*HID_];
__device__ bf16  g_wkvaT_p[(KVLORA_+DR_)*HID_];
__device__ bf16  g_wkvbT_h[H_*(DN_+DV_)*KVLORA_];
__device__ bf16  g_wkvbT_p[H_*(DN_+DV_)*KVLORA_];
__device__ bf16  g_woT_h  [HID_*H_*DV_];
__device__ bf16  g_woT_p  [HID_*H_*DV_];

/* --------------------------- helpers --------------------------------------- */
__device__ __forceinline__ uint32_t smem_u32(const void* p) {
    uint32_t a;
    asm("{ .reg .u64 t; cvta.to.shared.u64 t, %1; cvt.u32.u64 %0, t; }" : "=r"(a) : "l"(p));
    return a;
}
__device__ __forceinline__ void ldsm_x4(uint32_t& r0, uint32_t& r1, uint32_t& r2, uint32_t& r3,
                                        uint32_t addr) {
    asm volatile("ldmatrix.sync.aligned.m8n8.x4.shared.b16 {%0,%1,%2,%3}, [%4];"
                 : "=r"(r0), "=r"(r1), "=r"(r2), "=r"(r3) : "r"(addr));
}
__device__ __forceinline__ void mma16816(float* c, const uint32_t* a, uint32_t b0, uint32_t b1) {
    asm volatile("mma.sync.aligned.m16n8k16.row.col.f32.bf16.bf16.f32 "
                 "{%0,%1,%2,%3}, {%4,%5,%6,%7}, {%8,%9}, {%0,%1,%2,%3};"
                 : "+f"(c[0]), "+f"(c[1]), "+f"(c[2]), "+f"(c[3])
                 : "r"(a[0]), "r"(a[1]), "r"(a[2]), "r"(a[3]), "r"(b0), "r"(b1));
}
__device__ __forceinline__ void cpa16(uint32_t dst, const void* src) {
    asm volatile("cp.async.cg.shared.global [%0], [%1], 16;"
                 :: "r"(dst), "l"(src) : "memory");
}
#define CP_COMMIT() asm volatile("cp.async.commit_group;" ::: "memory")
#define CP_WAIT1()  asm volatile("cp.async.wait_group 1;" ::: "memory")

/* split 4 floats -> packed h (uint2) and primed p (uint2) */
__device__ __forceinline__ void split4p(float4 v, uint2& hh, uint2& pp) {
    float f[4] = {v.x, v.y, v.z, v.w};
    unsigned short h[4], p[4];
    #pragma unroll
    for (int i = 0; i < 4; i++) {
        bf16 hb = __float2bfloat16(f[i]);
        float hf = __bfloat162float(hb);
        bf16 pb = __float2bfloat16(fmaf(CSCALE_, f[i] - hf, hf));
        h[i] = *(unsigned short*)&hb;
        p[i] = *(unsigned short*)&pb;
    }
    hh.x = (uint32_t)h[0] | ((uint32_t)h[1] << 16);
    hh.y = (uint32_t)h[2] | ((uint32_t)h[3] << 16);
    pp.x = (uint32_t)p[0] | ((uint32_t)p[1] << 16);
    pp.y = (uint32_t)p[2] | ((uint32_t)p[3] << 16);
}
__device__ __forceinline__ void splitsc(float v, bf16& hb, bf16& pb) {
    hb = __float2bfloat16(v);
    float hf = __bfloat162float(hb);
    pb = __float2bfloat16(fmaf(CSCALE_, v - hf, hf));
}

/* FFMA-only exp */
__device__ __forceinline__ float fast_exp(float x) {
    float t = x * 1.4426950408889634f;
    float r = rintf(t);
    float f = t - r;
    float p =          1.339887440266574e-3f;
    p = fmaf(p, f,     9.618437357674640e-3f);
    p = fmaf(p, f,     5.550332471162809e-2f);
    p = fmaf(p, f,     2.402264791363012e-1f);
    p = fmaf(p, f,     6.931472028550421e-1f);
    p = fmaf(p, f,     1.0f);
    int ri = (int)r;
    if (ri < -126) ri = -126;
    float s = __int_as_float((uint32_t)(ri + 127) << 23);
    return p * s;
}

/* smem: K-chunk 64. A 128x64, B 128x64 bf16 (h and p); rows padded to 144B. */
#define ROWB   144
#define AH_O   0
#define AP_O   18432
#define BH_O   36864
#define BP_O   55296
#define STGSZ  73728
#define NSTG   3
#define GEMM_SMEM (NSTG*STGSZ)

/* -- bf16 HMMA GEMM: 128x128 CTA tile, 8 warps of 64x32, K-chunk 64,
   1 CTA of 256 thr, 3-stage cp.async (single barrier/chunk),
   2-pass scaled compensation: C = P + (Q-P)/16 ----------------------------- */
__global__ __launch_bounds__(256, 1) void mma_gemm10_kernel(
    const bf16* __restrict__ Ah_, const bf16* __restrict__ Ap_,
    const bf16* __restrict__ Bh_, const bf16* __restrict__ Bp_,
    float* __restrict__ Cf, bf16* __restrict__ Ch, bf16* __restrict__ Cp,
    int M, int N, int K, int lda, int ldb, int ldc,
    long long sA, long long sB, int zdiv, long long csOut, long long csIn,
    float alpha, int causalSkip, int causalK)
{
    const int row0 = blockIdx.y * 128;
    const int col0 = blockIdx.x * 128;
    if (causalSkip && col0 > row0 + 127) return;
    const int bz = blockIdx.z;
    const bf16* Ah = Ah_ + (long long)bz * sA;
    const bf16* Ap = Ap_ + (long long)bz * sA;
    const bf16* Bh = Bh_ + (long long)bz * sB;
    const bf16* Bp = Bp_ + (long long)bz * sB;
    const long long coff = (long long)(bz / zdiv) * csOut + (long long)(bz % zdiv) * csIn;

    extern __shared__ __align__(16) char smem[];
    const uint32_t sb = smem_u32(smem);

    const int tid  = threadIdx.x;
    const int wid  = tid >> 5;
    const int lane = tid & 31;
    const int wm = wid & 1;          /* M strip: rows wm*64..+64 */
    const int wn = wid >> 1;         /* N strip: cols wn*32..+32 */
    const int laneIn = lane & 7;
    const int quad   = lane >> 3;
    const int kofs   = wid & 3;

    const uint32_t aBase = (uint32_t)((wm * 64 + laneIn + (quad & 1) * 8) * ROWB
                                      + ((quad >> 1) * 8) * 2);
    const uint32_t bBase = (uint32_t)((wn * 32 + laneIn + (quad >> 1) * 8) * ROWB
                                      + ((quad & 1) * 8) * 2);

    int kend = K;
    if (causalK) { int kl = row0 + 128; if (kl < kend) kend = kl; }
    const int nch = kend >> 6;

    float accP[4][4][4], accQ[4][4][4];
    #pragma unroll
    for (int i = 0; i < 4; i++)
        #pragma unroll
        for (int j = 0; j < 4; j++)
            #pragma unroll
            for (int q = 0; q < 4; q++) { accP[i][j][q] = 0.0f; accQ[i][j][q] = 0.0f; }

    auto issue = [&](int s) {
        const uint32_t dst = sb + (uint32_t)(s % NSTG) * STGSZ;
        const int k0 = s << 6;
        /* A: 128 rows x 8 segs of 16B -> 4 per thread per operand */
        #pragma unroll
        for (int i = 0; i < 4; i++) {
            const int g = tid + i * 256;
            const int r = g >> 3, sg = g & 7;
            const uint32_t so = (uint32_t)(r * ROWB + sg * 16);
            const long long ga = (long long)(row0 + r) * lda + k0 + sg * 8;
            cpa16(dst + AH_O + so, Ah + ga);
            cpa16(dst + AP_O + so, Ap + ga);
        }
        /* B: 128 rows (N-dim) x 8 segs; clamp row for N not multiple of 128 */
        #pragma unroll
        for (int i = 0; i < 4; i++) {
            const int g = tid + i * 256;
            const int r = g >> 3, sg = g & 7;
            const int brow = col0 + r;
            const int brc = (brow < N) ? brow : (N - 1);
            const uint32_t so = (uint32_t)(r * ROWB + sg * 16);
            const long long gb = (long long)brc * ldb + k0 + sg * 8;
            cpa16(dst + BH_O + so, Bh + gb);
            cpa16(dst + BP_O + so, Bp + gb);
        }
    };

    /* prologue: 2 stages ahead */
    issue(0);
    CP_COMMIT();
    if (1 < nch) issue(1);
    CP_COMMIT();

    for (int c = 0; c < nch; c++) {
        CP_WAIT1();                 /* stage c landed */
        __syncthreads();            /* also: all warps done reading stage (c-1) */
        if (c + 2 < nch) issue(c + 2);
        CP_COMMIT();

        const uint32_t bufb = sb + (uint32_t)(c % NSTG) * STGSZ;
        #pragma unroll
        for (int ks = 0; ks < 4; ks++) {
            const int ksx = (ks + kofs) & 3;
            const uint32_t kb = (uint32_t)(ksx * 32);
            uint32_t bh[2][4], bp[2][4];
            #pragma unroll
            for (int np = 0; np < 2; np++) {
                const uint32_t bo = bBase + (uint32_t)(np * 16 * ROWB) + kb;
                ldsm_x4(bh[np][0], bh[np][1], bh[np][2], bh[np][3], bufb + BH_O + bo);
                ldsm_x4(bp[np][0], bp[np][1], bp[np][2], bp[np][3], bufb + BP_O + bo);
            }
            #pragma unroll
            for (int mt = 0; mt < 4; mt++) {
                uint32_t ah[4], ap[4];
                const uint32_t ao = aBase + (uint32_t)(mt * 16 * ROWB) + kb;
                ldsm_x4(ah[0], ah[1], ah[2], ah[3], bufb + AH_O + ao);
                ldsm_x4(ap[0], ap[1], ap[2], ap[3], bufb + AP_O + ao);
                #pragma unroll
                for (int nt = 0; nt < 4; nt++)
                    mma16816(accP[mt][nt], ah,
                             bh[nt >> 1][(nt & 1) * 2], bh[nt >> 1][(nt & 1) * 2 + 1]);
                #pragma unroll
                for (int nt = 0; nt < 4; nt++)
                    mma16816(accQ[mt][nt], ap,
                             bp[nt >> 1][(nt & 1) * 2], bp[nt >> 1][(nt & 1) * 2 + 1]);
            }
        }
    }

    /* epilogue: v = P + (Q-P)/16 */
    const int lr  = lane >> 2;
    const int lc2 = (lane & 3) * 2;
    #pragma unroll
    for (int mt = 0; mt < 4; mt++) {
        #pragma unroll
        for (int nt = 0; nt < 4; nt++) {
            const int gr = row0 + wm * 64 + mt * 16 + lr;
            const int gc = col0 + wn * 32 + nt * 8 + lc2;
            if (gc >= N) continue;
            float vv[4];
            #pragma unroll
            for (int q = 0; q < 4; q++)
                vv[q] = fmaf(accQ[mt][nt][q] - accP[mt][nt][q], CINV_, accP[mt][nt][q]) * alpha;
            const long long o0 = coff + (long long)gr * ldc + gc;
            const long long o1 = coff + (long long)(gr + 8) * ldc + gc;
            if (Cf) {
                *reinterpret_cast<float2*>(Cf + o0) = make_float2(vv[0], vv[1]);
                *reinterpret_cast<float2*>(Cf + o1) = make_float2(vv[2], vv[3]);
            }
            if (Ch) {
                bf16 h0, p0, h1, p1, h2, p2, h3, p3;
                splitsc(vv[0], h0, p0); splitsc(vv[1], h1, p1);
                splitsc(vv[2], h2, p2); splitsc(vv[3], h3, p3);
                __nv_bfloat162 hv0; hv0.x = h0; hv0.y = h1;
                __nv_bfloat162 hv1; hv1.x = h2; hv1.y = h3;
                __nv_bfloat162 pv0; pv0.x = p0; pv0.y = p1;
                __nv_bfloat162 pv1; pv1.x = p2; pv1.y = p3;
                *reinterpret_cast<__nv_bfloat162*>(Ch + o0) = hv0;
                *reinterpret_cast<__nv_bfloat162*>(Ch + o1) = hv1;
                *reinterpret_cast<__nv_bfloat162*>(Cp + o0) = pv0;
                *reinterpret_cast<__nv_bfloat162*>(Cp + o1) = pv1;
            }
        }
    }
}

/* ---------------- split fp32 -> h/p bf16 ------------------------------------ */
__global__ void split_kernel(const float* __restrict__ x, bf16* __restrict__ h,
                             bf16* __restrict__ p, int n4)
{
    int idx = blockIdx.x * blockDim.x + threadIdx.x;
    if (idx >= n4) return;
    float4 v = reinterpret_cast<const float4*>(x)[idx];
    uint2 hh, pp;
    split4p(v, hh, pp);
    reinterpret_cast<uint2*>(h)[idx] = hh;
    reinterpret_cast<uint2*>(p)[idx] = pp;
}

/* ---------------- transpose [K,N] fp32 -> [N,K] h/p bf16 -------------------- */
__global__ void transpose_split_kernel(const float* __restrict__ in,
                                       bf16* __restrict__ outH, bf16* __restrict__ outP,
                                       int K, int N)
{
    __shared__ float t[32][33];
    int k0 = blockIdx.y * 32, n0 = blockIdx.x * 32;
    int x = threadIdx.x, y = threadIdx.y;
    #pragma unroll
    for (int i = 0; i < 32; i += 8) {
        int k = k0 + y + i, n = n0 + x;
        t[y + i][x] = (k < K && n < N) ? in[(long long)k * N + n] : 0.0f;
    }
    __syncthreads();
    #pragma unroll
    for (int i = 0; i < 32; i += 8) {
        int n = n0 + y + i, k = k0 + x;
        if (n < N && k < K) {
            bf16 hb, pb;
            splitsc(t[x][y + i], hb, pb);
            outH[(long long)n * K + k] = hb;
            outP[(long long)n * K + k] = pb;
        }
    }
}

/* ---------------- RMS norm -> h/p ------------------------------------------- */
__global__ __launch_bounds__(256) void rmsnorm_split_kernel(
    const float* __restrict__ x, const float* __restrict__ w,
    bf16* __restrict__ yh, bf16* __restrict__ yp, int n, int ldx, int ldy)
{
    int row = blockIdx.x;
    const float* xr = x + (long long)row * ldx;
    int tid = threadIdx.x;
    float ss = 0.0f;
    for (int i = tid; i < n; i += 256) { float v = xr[i]; ss += v * v; }
    __shared__ float red[8];
    #pragma unroll
    for (int o = 16; o; o >>= 1) ss += __shfl_xor_sync(0xffffffffu, ss, o);
    if ((tid & 31) == 0) red[tid >> 5] = ss;
    __syncthreads();
    if (tid < 32) {
        float v = (tid < 8) ? red[tid] : 0.0f;
        #pragma unroll
        for (int o = 4; o; o >>= 1) v += __shfl_xor_sync(0xffffffffu, v, o);
        if (tid == 0) red[0] = v;
    }
    __syncthreads();
    float inv = rsqrtf(red[0] / (float)n + 1e-6f);
    bf16* yhr = yh + (long long)row * ldy;
    bf16* ypr = yp + (long long)row * ldy;
    for (int i = tid; i < n; i += 256) {
        bf16 hb, pb;
        splitsc(w[i] * xr[i] * inv, hb, pb);
        yhr[i] = hb;
        ypr[i] = pb;
    }
}

/* ---------------- q rope -> qfull h/p ---------------------------------------- */
__global__ void qrope_split_kernel(const float* __restrict__ qf, const float* __restrict__ cs,
                                   const float* __restrict__ sn,
                                   bf16* __restrict__ oh, bf16* __restrict__ op)
{
    int idx = blockIdx.x * blockDim.x + threadIdx.x;
    const int total4 = B_ * H_ * S_ * (DQK_ / 4);
    if (idx >= total4) return;
    int d4 = idx % (DQK_ / 4);
    int t = idx / (DQK_ / 4);
    int s = t % S_; t /= S_;
    int h = t % H_;
    int b = t / H_;
    int d = d4 * 4;
    const float* src = qf + (((long long)(b * S_ + s)) * H_ + h) * DQK_;
    float4 val;
    if (d < DN_) {
        val = *reinterpret_cast<const float4*>(src + d);
    } else {
        int p = d - DN_;
        float4 x = *reinterpret_cast<const float4*>(src + DN_ + p);
        float4 other;
        if (p < DR_ / 2) {
            float4 o = *reinterpret_cast<const float4*>(src + DN_ + p + DR_ / 2);
            other = make_float4(-o.x, -o.y, -o.z, -o.w);
        } else {
            other = *reinterpret_cast<const float4*>(src + DN_ + p - DR_ / 2);
        }
        long long co = ((long long)b * S_ + s) * DR_ + p;
        float4 c = *reinterpret_cast<const float4*>(cs + co);
        float4 ss2 = *reinterpret_cast<const float4*>(sn + co);
        val.x = fmaf(x.x, c.x, other.x * ss2.x);
        val.y = fmaf(x.y, c.y, other.y * ss2.y);
        val.z = fmaf(x.z, c.z, other.z * ss2.z);
        val.w = fmaf(x.w, c.w, other.w * ss2.w);
    }
    uint2 hh, pp;
    split4p(val, hh, pp);
    reinterpret_cast<uint2*>(oh)[idx] = hh;
    reinterpret_cast<uint2*>(op)[idx] = pp;
}

__global__ void krope_kernel(const float* __restrict__ ckv, const float* __restrict__ cs,
                             const float* __restrict__ sn, float* __restrict__ kpe)
{
    int idx = blockIdx.x * blockDim.x + threadIdx.x;
    if (idx >= B_ * S_ * (DR_ / 4)) return;
    int p4 = idx % (DR_ / 4);
    int bs = idx / (DR_ / 4);
    int p = p4 * 4;
    const float* src = ckv + (long long)bs * (KVLORA_ + DR_) + KVLORA_;
    float4 x = *reinterpret_cast<const float4*>(src + p);
    float4 other;
    if (p < DR_ / 2) {
        float4 o = *reinterpret_cast<const float4*>(src + p + DR_ / 2);
        other = make_float4(-o.x, -o.y, -o.z, -o.w);
    } else {
        other = *reinterpret_cast<const float4*>(src + p - DR_ / 2);
    }
    long long co = (long long)bs * DR_ + p;
    float4 c = *reinterpret_cast<const float4*>(cs + co);
    float4 ss2 = *reinterpret_cast<const float4*>(sn + co);
    float4 val;
    val.x = fmaf(x.x, c.x, other.x * ss2.x);
    val.y = fmaf(x.y, c.y, other.y * ss2.y);
    val.z = fmaf(x.z, c.z, other.z * ss2.z);
    val.w = fmaf(x.w, c.w, other.w * ss2.w);
    *reinterpret_cast<float4*>(kpe + co) = val;
}

__global__ void kbuild_split_kernel(const float* __restrict__ kvflat, const float* __restrict__ kpe,
                                    bf16* __restrict__ oh, bf16* __restrict__ op)
{
    int idx = blockIdx.x * blockDim.x + threadIdx.x;
    const int total4 = B_ * H_ * S_ * (DQK_ / 4);
    if (idx >= total4) return;
    int d4 = idx % (DQK_ / 4);
    int t = idx / (DQK_ / 4);
    int s = t % S_; t /= S_;
    int h = t % H_;
    int b = t / H_;
    int d = d4 * 4;
    float4 val;
    if (d < DN_)
        val = *reinterpret_cast<const float4*>(
            kvflat + (((long long)(b * S_ + s)) * H_ + h) * (DN_ + DV_) + d);
    else
        val = *reinterpret_cast<const float4*>(
            kpe + ((long long)b * S_ + s) * DR_ + (d - DN_));
    uint2 hh, pp;
    split4p(val, hh, pp);
    reinterpret_cast<uint2*>(oh)[idx] = hh;
    reinterpret_cast<uint2*>(op)[idx] = pp;
}

/* v transpose -> vT h/p [b,h,d,s] */
__global__ void vbuildT_split_kernel(const float* __restrict__ kvflat,
                                     bf16* __restrict__ oh, bf16* __restrict__ op)
{
    __shared__ float t[32][33];
    int bh = blockIdx.z;
    int b = bh >> 4, h = bh & 15;
    int s0 = blockIdx.x * 32, d0 = blockIdx.y * 32;
    int x = threadIdx.x, y = threadIdx.y;
    const float* src = kvflat + ((long long)b * S_ * H_ + h) * (DN_ + DV_) + DN_;
    #pragma unroll
    for (int i = 0; i < 32; i += 8) {
        int s = s0 + y + i, d = d0 + x;
        t[y + i][x] = src[(long long)s * (H_ * (DN_ + DV_)) + d];
    }
    __syncthreads();
    long long base = ((long long)bh * DV_) * S_;
    #pragma unroll
    for (int i = 0; i < 32; i += 8) {
        int d = d0 + y + i, s = s0 + x;
        bf16 hb, pb;
        splitsc(t[x][y + i], hb, pb);
        oh[base + (long long)d * S_ + s] = hb;
        op[base + (long long)d * S_ + s] = pb;
    }
}

/* -- causal softmax: logits in h/p bf16; writes fp32 weights + h/p ----------- */
__global__ __launch_bounds__(256) void softmax_kernel(float* __restrict__ wts,
                                                      bf16* __restrict__ wh,
                                                      bf16* __restrict__ wp)
{
    long long row = blockIdx.x;
    int i = (int)(row % S_);
    float* r = wts + row * (long long)S_;
    bf16* rh = wh + row * (long long)S_;
    bf16* rp = wp + row * (long long)S_;
    int tid = threadIdx.x;
    int nvalid = i + 1;

    float e[8];
    float mx = -1e30f;
    int cnt = 0;
    for (int j = tid; j < nvalid; j += 256) {
        float hv = __bfloat162float(rh[j]);
        float pv = __bfloat162float(rp[j]);
        e[cnt] = fmaf(pv - hv, CINV_, hv);
        mx = fmaxf(mx, e[cnt]);
        cnt++;
    }

    __shared__ float sm[8];
    #pragma unroll
    for (int o = 16; o; o >>= 1) mx = fmaxf(mx, __shfl_xor_sync(0xffffffffu, mx, o));
    if ((tid & 31) == 0) sm[tid >> 5] = mx;
    __syncthreads();
    if (tid < 32) {
        float v = (tid < 8) ? sm[tid] : -1e30f;
        #pragma unroll
        for (int o = 4; o; o >>= 1) v = fmaxf(v, __shfl_xor_sync(0xffffffffu, v, o));
        if (tid == 0) sm[0] = v;
    }
    __syncthreads();
    mx = sm[0];
    __syncthreads();

    float sum = 0.0f;
    cnt = 0;
    for (int j = tid; j < nvalid; j += 256) {
        float ev = fast_exp(e[cnt] - mx);
        e[cnt] = ev;
        sum += ev;
        cnt++;
    }
    #pragma unroll
    for (int o = 16; o; o >>= 1) sum += __shfl_xor_sync(0xffffffffu, sum, o);
    if ((tid & 31) == 0) sm[tid >> 5] = sum;
    __syncthreads();
    if (tid < 32) {
        float v = (tid < 8) ? sm[tid] : 0.0f;
        #pragma unroll
        for (int o = 4; o; o >>= 1) v += __shfl_xor_sync(0xffffffffu, v, o);
        if (tid == 0) sm[0] = v;
    }
    __syncthreads();
    float inv = 1.0f / sm[0];

    cnt = 0;
    for (int j = tid; j < nvalid; j += 256) {
        float v = e[cnt] * inv;
        r[j] = v;
        bf16 hb, pb;
        splitsc(v, hb, pb);
        rh[j] = hb;
        rp[j] = pb;
        cnt++;
    }
    int bound = ((i >> 7) + 1) << 7;
    bf16 z = __float2bfloat16(0.0f);
    for (int j = nvalid + tid; j < bound; j += 256) { rh[j] = z; rp[j] = z; }
    for (int j = nvalid + tid; j < S_; j += 256) r[j] = 0.0f;
}

/* ---------------- host ------------------------------------------------------ */
static inline void mma_gemm(const bf16* Ah, const bf16* Ap, const bf16* Bh, const bf16* Bp,
                            float* Cf, bf16* Ch, bf16* Cp,
                            int M, int N, int K, int lda, int ldb, int ldc,
                            long long sA, long long sB,
                            int zdiv, long long csOut, long long csIn,
                            float alpha, int causalSkip, int causalK, int batch)
{
    dim3 grid((N + 127) / 128, (M + 127) / 128, batch);
    mma_gemm10_kernel<<<grid, 256, GEMM_SMEM>>>(Ah, Ap, Bh, Bp, Cf, Ch, Cp,
                                                M, N, K, lda, ldb, ldc,
                                                sA, sB, zdiv, csOut, csIn,
                                                alpha, causalSkip, causalK);
}

extern "C" void kernel_launch(void* const* d_in, const int* in_sizes, int n_in,
                              void* d_out, int out_size)
{
    const float* hs      = (const float*)d_in[0];
    const float* cs      = (const float*)d_in[1];
    const float* sn      = (const float*)d_in[2];
    const float* q_a_w   = (const float*)d_in[4];
    const float* q_a_ln  = (const float*)d_in[5];
    const float* q_b_w   = (const float*)d_in[6];
    const float* kv_a_w  = (const float*)d_in[7];
    const float* kv_a_ln = (const float*)d_in[8];
    const float* kv_b_w  = (const float*)d_in[9];
    const float* o_w     = (const float*)d_in[10];

    float* out = (float*)d_out;
    float* wts = out + (long long)B_ * S_ * HID_;

    static bool attr_set = false;
    if (!attr_set) {
        cudaFuncSetAttribute(mma_gemm10_kernel, cudaFuncAttributeMaxDynamicSharedMemorySize, GEMM_SMEM);
        attr_set = true;
    }

#define GETSYM(p, s) cudaGetSymbolAddress((void**)&p, s)
    bf16 *hsh, *hsp, *qlnh, *qlnp, *qfh, *qfp, *kch, *kcp, *kfh, *kfp, *vth, *vtp;
    bf16 *whh, *whp, *omh, *omp;
    bf16 *wqah, *wqap, *wqbh, *wqbp, *wkah, *wkap, *wkbh, *wkbp, *woh, *wop;
    float *qlat, *qflat, *ckv, *kpe, *kvflat;
    GETSYM(hsh, g_hs_h);    GETSYM(hsp, g_hs_p);
    GETSYM(qlat, g_qlat);   GETSYM(qlnh, g_qlatn_h);  GETSYM(qlnp, g_qlatn_p);
    GETSYM(qflat, g_qflat); GETSYM(qfh, g_qfull_h);   GETSYM(qfp, g_qfull_p);
    GETSYM(ckv, g_ckv);     GETSYM(kch, g_kc_h);      GETSYM(kcp, g_kc_p);
    GETSYM(kpe, g_kpe);     GETSYM(kvflat, g_kvflat);
    GETSYM(kfh, g_kfull_h); GETSYM(kfp, g_kfull_p);
    GETSYM(vth, g_vT_h);    GETSYM(vtp, g_vT_p);
    GETSYM(whh, g_w_h);     GETSYM(whp, g_w_p);
    GETSYM(omh, g_omid_h);  GETSYM(omp, g_omid_p);
    GETSYM(wqah, g_wqaT_h); GETSYM(wqap, g_wqaT_p);
    GETSYM(wqbh, g_wqbT_h); GETSYM(wqbp, g_wqbT_p);
    GETSYM(wkah, g_wkvaT_h); GETSYM(wkap, g_wkvaT_p);
    GETSYM(wkbh, g_wkvbT_h); GETSYM(wkbp, g_wkvbT_p);
    GETSYM(woh, g_woT_h);   GETSYM(wop, g_woT_p);
#undef GETSYM

    dim3 tb(32, 8);
    /* 0 */ transpose_split_kernel<<<dim3(QLORA_ / 32, HID_ / 32), tb>>>(q_a_w, wqah, wqap, HID_, QLORA_);
    /* 1 */ split_kernel<<<(NTOK_ * HID_ / 4 + 255) / 256, 256>>>(hs, hsh, hsp, NTOK_ * HID_ / 4);
    /* 2 */ transpose_split_kernel<<<dim3((KVLORA_ + DR_) / 32, HID_ / 32), tb>>>(kv_a_w, wkah, wkap, HID_, KVLORA_ + DR_);
    /* 3 q_a (profiled) */
    mma_gemm(hsh, hsp, wqah, wqap, qlat, 0, 0,
             NTOK_, QLORA_, HID_, HID_, HID_, QLORA_,
             0, 0, 1, 0, 0, 1.0f, 0, 0, 1);
    /* 4 kv_a */
    mma_gemm(hsh, hsp, wkah, wkap, ckv, 0, 0,
             NTOK_, KVLORA_ + DR_, HID_, HID_, HID_, KVLORA_ + DR_,
             0, 0, 1, 0, 0, 1.0f, 0, 0, 1);
    /* 5 */ rmsnorm_split_kernel<<<NTOK_, 256>>>(qlat, q_a_ln, qlnh, qlnp, QLORA_, QLORA_, QLORA_);
    /* 6 */ transpose_split_kernel<<<dim3(H_ * DQK_ / 32, QLORA_ / 32), tb>>>(q_b_w, wqbh, wqbp, QLORA_, H_ * DQK_);
    /* 7 q_b */
    mma_gemm(qlnh, qlnp, wqbh, wqbp, qflat, 0, 0,
             NTOK_, H_ * DQK_, QLORA_, QLORA_, QLORA_, H_ * DQK_,
             0, 0, 1, 0, 0, 1.0f, 0, 0, 1);
    /* 8 */ qrope_split_kernel<<<(B_ * H_ * S_ * (DQK_ / 4) + 255) / 256, 256>>>(qflat, cs, sn, qfh, qfp);
    /* 9 */ rmsnorm_split_kernel<<<NTOK_, 256>>>(ckv, kv_a_ln, kch, kcp, KVLORA_, KVLORA_ + DR_, KVLORA_);
    /* 10 */ krope_kernel<<<(B_ * S_ * (DR_ / 4) + 255) / 256, 256>>>(ckv, cs, sn, kpe);
    /* 11 */ transpose_split_kernel<<<dim3(H_ * (DN_ + DV_) / 32, KVLORA_ / 32), tb>>>(kv_b_w, wkbh, wkbp, KVLORA_, H_ * (DN_ + DV_));
    /* 12 kv_b */
    mma_gemm(kch, kcp, wkbh, wkbp, kvflat, 0, 0,
             NTOK_, H_ * (DN_ + DV_), KVLORA_, KVLORA_, KVLORA_, H_ * (DN_ + DV_),
             0, 0, 1, 0, 0, 1.0f, 0, 0, 1);
    /* 13 */ kbuild_split_kernel<<<(B_ * H_ * S_ * (DQK_ / 4) + 255) / 256, 256>>>(kvflat, kpe, kfh, kfp);
    /* 14 */ vbuildT_split_kernel<<<dim3(S_ / 32, DV_ / 32, B_ * H_), tb>>>(kvflat, vth, vtp);
    /* 15 scores -> h/p logits */
    mma_gemm(qfh, qfp, kfh, kfp, 0, whh, whp,
             S_, S_, DQK_, DQK_, DQK_, S_,
             (long long)S_ * DQK_, (long long)S_ * DQK_,
             1, (long long)S_ * S_, 0,
             SCALING_, 1, 0, B_ * H_);
    /* 16 softmax */
    softmax_kernel<<<B_ * H_ * S_, 256>>>(wts, whh, whp);
    /* 17 PV -> omid h/p */
    mma_gemm(whh, whp, vth, vtp, 0, omh, omp,
             S_, DV_, S_, S_, S_, H_ * DV_,
             (long long)S_ * S_, (long long)DV_ * S_,
             H_, (long long)S_ * H_ * DV_, (long long)DV_,
             1.0f, 0, 1, B_ * H_);
    /* 18 */ transpose_split_kernel<<<dim3(HID_ / 32, (H_ * DV_) / 32), tb>>>(o_w, woh, wop, H_ * DV_, HID_);
    /* 19 o_proj */
    mma_gemm(omh, omp, woh, wop, out, 0, 0,
             NTOK_, HID_, H_ * DV_, H_ * DV_, H_ * DV_, HID_,
             0, 0, 1, 0, 0, 1.0f, 0, 0, 1);
}

// round 14
// speedup vs baseline: 1.1204x; 1.1204x over previous
#include <cuda_runtime.h>
#include <cuda_bf16.h>
#include <math.h>
#include <stdint.h>

#define B_      2
#define S_      2048
#define HID_    2048
#define H_      16
#define QLORA_  1536
#define KVLORA_ 512
#define DR_     64
#define DN_     128
#define DQK_    192
#define DV_     128
#define NTOK_   (B_*S_)
#define QKVN_   (QLORA_+KVLORA_+DR_)   /* 2112 */
#define SCALING_ 0.07216878364870322f
#define CSCALE_ 16.0f
#define CINV_   0.0625f

typedef __nv_bfloat16 bf16;

/* scratch: "h" = bf16(x), "p" = bf16(h + 16*(x-h)) */
__device__ bf16  g_hs_h [NTOK_*HID_];
__device__ bf16  g_hs_p [NTOK_*HID_];
__device__ float g_qkvlat[NTOK_*QKVN_];          /* [qlat(1536) | kc(512) | kpe(64)] */
__device__ bf16  g_qlatn_h[NTOK_*QLORA_];
__device__ bf16  g_qlatn_p[NTOK_*QLORA_];
__device__ float g_qflat [NTOK_*H_*DQK_];
__device__ bf16  g_qfull_h[B_*H_*S_*DQK_];
__device__ bf16  g_qfull_p[B_*H_*S_*DQK_];
__device__ bf16  g_kc_h [NTOK_*KVLORA_];
__device__ bf16  g_kc_p [NTOK_*KVLORA_];
__device__ float g_kpe   [B_*S_*DR_];
__device__ float g_kvflat[NTOK_*H_*(DN_+DV_)];
__device__ bf16  g_kfull_h[B_*H_*S_*DQK_];
__device__ bf16  g_kfull_p[B_*H_*S_*DQK_];
__device__ bf16  g_vT_h [B_*H_*DV_*S_];
__device__ bf16  g_vT_p [B_*H_*DV_*S_];
__device__ bf16  g_w_h  [(long long)B_*H_*S_*S_];
__device__ bf16  g_w_p  [(long long)B_*H_*S_*S_];
__device__ bf16  g_omid_h[NTOK_*H_*DV_];
__device__ bf16  g_omid_p[NTOK_*H_*DV_];
__device__ bf16  g_wqkvT_h[QKVN_*HID_];
__device__ bf16  g_wqkvT_p[QKVN_*HID_];
__device__ bf16  g_wqbT_h [H_*DQK_*QLORA_];
__device__ bf16  g_wqbT_p [H_*DQK_*QLORA_];
__device__ bf16  g_wkvbT_h[H_*(DN_+DV_)*KVLORA_];
__device__ bf16  g_wkvbT_p[H_*(DN_+DV_)*KVLORA_];
__device__ bf16  g_woT_h  [HID_*H_*DV_];
__device__ bf16  g_woT_p  [HID_*H_*DV_];

/* --------------------------- helpers --------------------------------------- */
__device__ __forceinline__ uint32_t smem_u32(const void* p) {
    uint32_t a;
    asm("{ .reg .u64 t; cvta.to.shared.u64 t, %1; cvt.u32.u64 %0, t; }" : "=r"(a) : "l"(p));
    return a;
}
__device__ __forceinline__ void ldsm_x4(uint32_t& r0, uint32_t& r1, uint32_t& r2, uint32_t& r3,
                                        uint32_t addr) {
    asm volatile("ldmatrix.sync.aligned.m8n8.x4.shared.b16 {%0,%1,%2,%3}, [%4];"
                 : "=r"(r0), "=r"(r1), "=r"(r2), "=r"(r3) : "r"(addr));
}
__device__ __forceinline__ void mma16816(float* c, const uint32_t* a, uint32_t b0, uint32_t b1) {
    asm volatile("mma.sync.aligned.m16n8k16.row.col.f32.bf16.bf16.f32 "
                 "{%0,%1,%2,%3}, {%4,%5,%6,%7}, {%8,%9}, {%0,%1,%2,%3};"
                 : "+f"(c[0]), "+f"(c[1]), "+f"(c[2]), "+f"(c[3])
                 : "r"(a[0]), "r"(a[1]), "r"(a[2]), "r"(a[3]), "r"(b0), "r"(b1));
}
__device__ __forceinline__ void cpa16(uint32_t dst, const void* src) {
    asm volatile("cp.async.cg.shared.global [%0], [%1], 16;"
                 :: "r"(dst), "l"(src) : "memory");
}
#define CP_COMMIT() asm volatile("cp.async.commit_group;" ::: "memory")
#define CP_WAIT1()  asm volatile("cp.async.wait_group 1;" ::: "memory")

__device__ __forceinline__ void split4p(float4 v, uint2& hh, uint2& pp) {
    float f[4] = {v.x, v.y, v.z, v.w};
    unsigned short h[4], p[4];
    #pragma unroll
    for (int i = 0; i < 4; i++) {
        bf16 hb = __float2bfloat16(f[i]);
        float hf = __bfloat162float(hb);
        bf16 pb = __float2bfloat16(fmaf(CSCALE_, f[i] - hf, hf));
        h[i] = *(unsigned short*)&hb;
        p[i] = *(unsigned short*)&pb;
    }
    hh.x = (uint32_t)h[0] | ((uint32_t)h[1] << 16);
    hh.y = (uint32_t)h[2] | ((uint32_t)h[3] << 16);
    pp.x = (uint32_t)p[0] | ((uint32_t)p[1] << 16);
    pp.y = (uint32_t)p[2] | ((uint32_t)p[3] << 16);
}
__device__ __forceinline__ void splitsc(float v, bf16& hb, bf16& pb) {
    hb = __float2bfloat16(v);
    float hf = __bfloat162float(hb);
    pb = __float2bfloat16(fmaf(CSCALE_, v - hf, hf));
}

/* FFMA-only exp */
__device__ __forceinline__ float fast_exp(float x) {
    float t = x * 1.4426950408889634f;
    float r = rintf(t);
    float f = t - r;
    float p =          1.339887440266574e-3f;
    p = fmaf(p, f,     9.618437357674640e-3f);
    p = fmaf(p, f,     5.550332471162809e-2f);
    p = fmaf(p, f,     2.402264791363012e-1f);
    p = fmaf(p, f,     6.931472028550421e-1f);
    p = fmaf(p, f,     1.0f);
    int ri = (int)r;
    if (ri < -126) ri = -126;
    float s = __int_as_float((uint32_t)(ri + 127) << 23);
    return p * s;
}

/* smem: K-chunk 64. A tiles 128x64 bf16, B 64x64; rows padded to 144B. */
#define ROWB   144
#define AH_O   0
#define AP_O   18432
#define BH_O   36864
#define BP_O   46080
#define STGSZ  55296
#define NSTG   2
#define GEMM_SMEM (NSTG*STGSZ)

/* -- bf16 HMMA GEMM: 128x64 CTA, 8 warps 32x32, K-chunk 64, 2 CTAs/SM,
   2-pass scaled compensation C = P + (Q-P)/16, warp-staggered ks phases --- */
__global__ __launch_bounds__(256, 2) void mma_gemm9_kernel(
    const bf16* __restrict__ Ah_, const bf16* __restrict__ Ap_,
    const bf16* __restrict__ Bh_, const bf16* __restrict__ Bp_,
    float* __restrict__ Cf, bf16* __restrict__ Ch, bf16* __restrict__ Cp,
    int M, int N, int K, int lda, int ldb, int ldc,
    long long sA, long long sB, int zdiv, long long csOut, long long csIn,
    float alpha, int causalSkip, int causalK)
{
    const int row0 = blockIdx.y * 128;
    const int col0 = blockIdx.x * 64;
    if (causalSkip && col0 > row0 + 127) return;
    const int bz = blockIdx.z;
    const bf16* Ah = Ah_ + (long long)bz * sA;
    const bf16* Ap = Ap_ + (long long)bz * sA;
    const bf16* Bh = Bh_ + (long long)bz * sB;
    const bf16* Bp = Bp_ + (long long)bz * sB;
    const long long coff = (long long)(bz / zdiv) * csOut + (long long)(bz % zdiv) * csIn;

    extern __shared__ __align__(16) char smem[];
    const uint32_t sb = smem_u32(smem);

    const int tid  = threadIdx.x;
    const int wid  = tid >> 5;
    const int lane = tid & 31;
    const int wm = wid & 3;
    const int wn = wid >> 2;
    const int laneIn = lane & 7;
    const int quad   = lane >> 3;
    const int kofs   = wid & 3;

    const uint32_t aBase = (uint32_t)((wm * 32 + laneIn + (quad & 1) * 8) * ROWB
                                      + ((quad >> 1) * 8) * 2);
    const uint32_t bBase = (uint32_t)((wn * 32 + laneIn + (quad >> 1) * 8) * ROWB
                                      + ((quad & 1) * 8) * 2);

    int kend = K;
    if (causalK) { int kl = row0 + 128; if (kl < kend) kend = kl; }
    const int nch = kend >> 6;

    float accP[2][4][4], accQ[2][4][4];
    #pragma unroll
    for (int i = 0; i < 2; i++)
        #pragma unroll
        for (int j = 0; j < 4; j++)
            #pragma unroll
            for (int q = 0; q < 4; q++) { accP[i][j][q] = 0.0f; accQ[i][j][q] = 0.0f; }

    auto issue = [&](int s) {
        const uint32_t dst = sb + (uint32_t)(s & 1) * STGSZ;
        const int k0 = s << 6;
        #pragma unroll
        for (int i = 0; i < 4; i++) {
            const int g = tid + i * 256;
            const int r = g >> 3, sg = g & 7;
            const uint32_t so = (uint32_t)(r * ROWB + sg * 16);
            const long long ga = (long long)(row0 + r) * lda + k0 + sg * 8;
            cpa16(dst + AH_O + so, Ah + ga);
            cpa16(dst + AP_O + so, Ap + ga);
        }
        #pragma unroll
        for (int i = 0; i < 2; i++) {
            const int g = tid + i * 256;
            const int r = g >> 3, sg = g & 7;
            const uint32_t so = (uint32_t)(r * ROWB + sg * 16);
            const long long gb = (long long)(col0 + r) * ldb + k0 + sg * 8;
            cpa16(dst + BH_O + so, Bh + gb);
            cpa16(dst + BP_O + so, Bp + gb);
        }
    };

    issue(0);
    CP_COMMIT();

    for (int c = 0; c < nch; c++) {
        if (c + 1 < nch) issue(c + 1);
        CP_COMMIT();
        CP_WAIT1();
        __syncthreads();

        const uint32_t bufb = sb + (uint32_t)(c & 1) * STGSZ;
        #pragma unroll
        for (int ks = 0; ks < 4; ks++) {
            const int ksx = (ks + kofs) & 3;
            const uint32_t kb = (uint32_t)(ksx * 32);
            uint32_t ah[2][4], ap[2][4], bh[2][4], bp[2][4];
            #pragma unroll
            for (int mt = 0; mt < 2; mt++) {
                const uint32_t ao = aBase + (uint32_t)(mt * 16 * ROWB) + kb;
                ldsm_x4(ah[mt][0], ah[mt][1], ah[mt][2], ah[mt][3], bufb + AH_O + ao);
                ldsm_x4(ap[mt][0], ap[mt][1], ap[mt][2], ap[mt][3], bufb + AP_O + ao);
            }
            #pragma unroll
            for (int np = 0; np < 2; np++) {
                const uint32_t bo = bBase + (uint32_t)(np * 16 * ROWB) + kb;
                ldsm_x4(bh[np][0], bh[np][1], bh[np][2], bh[np][3], bufb + BH_O + bo);
                ldsm_x4(bp[np][0], bp[np][1], bp[np][2], bp[np][3], bufb + BP_O + bo);
            }
            #pragma unroll
            for (int mt = 0; mt < 2; mt++)
                #pragma unroll
                for (int nt = 0; nt < 4; nt++)
                    mma16816(accP[mt][nt], ah[mt],
                             bh[nt >> 1][(nt & 1) * 2], bh[nt >> 1][(nt & 1) * 2 + 1]);
            #pragma unroll
            for (int mt = 0; mt < 2; mt++)
                #pragma unroll
                for (int nt = 0; nt < 4; nt++)
                    mma16816(accQ[mt][nt], ap[mt],
                             bp[nt >> 1][(nt & 1) * 2], bp[nt >> 1][(nt & 1) * 2 + 1]);
        }
        __syncthreads();
    }

    const int lr  = lane >> 2;
    const int lc2 = (lane & 3) * 2;
    #pragma unroll
    for (int mt = 0; mt < 2; mt++) {
        #pragma unroll
        for (int nt = 0; nt < 4; nt++) {
            const int gr = row0 + wm * 32 + mt * 16 + lr;
            const int gc = col0 + wn * 32 + nt * 8 + lc2;
            float vv[4];
            #pragma unroll
            for (int q = 0; q < 4; q++)
                vv[q] = fmaf(accQ[mt][nt][q] - accP[mt][nt][q], CINV_, accP[mt][nt][q]) * alpha;
            const long long o0 = coff + (long long)gr * ldc + gc;
            const long long o1 = coff + (long long)(gr + 8) * ldc + gc;
            if (Cf) {
                *reinterpret_cast<float2*>(Cf + o0) = make_float2(vv[0], vv[1]);
                *reinterpret_cast<float2*>(Cf + o1) = make_float2(vv[2], vv[3]);
            }
            if (Ch) {
                bf16 h0, p0, h1, p1, h2, p2, h3, p3;
                splitsc(vv[0], h0, p0); splitsc(vv[1], h1, p1);
                splitsc(vv[2], h2, p2); splitsc(vv[3], h3, p3);
                __nv_bfloat162 hv0; hv0.x = h0; hv0.y = h1;
                __nv_bfloat162 hv1; hv1.x = h2; hv1.y = h3;
                __nv_bfloat162 pv0; pv0.x = p0; pv0.y = p1;
                __nv_bfloat162 pv1; pv1.x = p2; pv1.y = p3;
                *reinterpret_cast<__nv_bfloat162*>(Ch + o0) = hv0;
                *reinterpret_cast<__nv_bfloat162*>(Ch + o1) = hv1;
                *reinterpret_cast<__nv_bfloat162*>(Cp + o0) = pv0;
                *reinterpret_cast<__nv_bfloat162*>(Cp + o1) = pv1;
            }
        }
    }
}

/* ---------------- split fp32 -> h/p bf16 ------------------------------------ */
__global__ void split_kernel(const float* __restrict__ x, bf16* __restrict__ h,
                             bf16* __restrict__ p, int n4)
{
    int idx = blockIdx.x * blockDim.x + threadIdx.x;
    if (idx >= n4) return;
    float4 v = reinterpret_cast<const float4*>(x)[idx];
    uint2 hh, pp;
    split4p(v, hh, pp);
    reinterpret_cast<uint2*>(h)[idx] = hh;
    reinterpret_cast<uint2*>(p)[idx] = pp;
}

/* ---------------- transpose [K,N] fp32 -> [N,K] h/p bf16 -------------------- */
__global__ void transpose_split_kernel(const float* __restrict__ in,
                                       bf16* __restrict__ outH, bf16* __restrict__ outP,
                                       int K, int N)
{
    __shared__ float t[32][33];
    int k0 = blockIdx.y * 32, n0 = blockIdx.x * 32;
    int x = threadIdx.x, y = threadIdx.y;
    #pragma unroll
    for (int i = 0; i < 32; i += 8) {
        int k = k0 + y + i, n = n0 + x;
        t[y + i][x] = (k < K && n < N) ? in[(long long)k * N + n] : 0.0f;
    }
    __syncthreads();
    #pragma unroll
    for (int i = 0; i < 32; i += 8) {
        int n = n0 + y + i, k = k0 + x;
        if (n < N && k < K) {
            bf16 hb, pb;
            splitsc(t[x][y + i], hb, pb);
            outH[(long long)n * K + k] = hb;
            outP[(long long)n * K + k] = pb;
        }
    }
}

/* ---------------- RMS norm -> h/p ------------------------------------------- */
__global__ __launch_bounds__(256) void rmsnorm_split_kernel(
    const float* __restrict__ x, const float* __restrict__ w,
    bf16* __restrict__ yh, bf16* __restrict__ yp, int n, int ldx, int ldy)
{
    int row = blockIdx.x;
    const float* xr = x + (long long)row * ldx;
    int tid = threadIdx.x;
    float ss = 0.0f;
    for (int i = tid; i < n; i += 256) { float v = xr[i]; ss += v * v; }
    __shared__ float red[8];
    #pragma unroll
    for (int o = 16; o; o >>= 1) ss += __shfl_xor_sync(0xffffffffu, ss, o);
    if ((tid & 31) == 0) red[tid >> 5] = ss;
    __syncthreads();
    if (tid < 32) {
        float v = (tid < 8) ? red[tid] : 0.0f;
        #pragma unroll
        for (int o = 4; o; o >>= 1) v += __shfl_xor_sync(0xffffffffu, v, o);
        if (tid == 0) red[0] = v;
    }
    __syncthreads();
    float inv = rsqrtf(red[0] / (float)n + 1e-6f);
    bf16* yhr = yh + (long long)row * ldy;
    bf16* ypr = yp + (long long)row * ldy;
    for (int i = tid; i < n; i += 256) {
        bf16 hb, pb;
        splitsc(w[i] * xr[i] * inv, hb, pb);
        yhr[i] = hb;
        ypr[i] = pb;
    }
}

/* ---------------- q rope -> qfull h/p ---------------------------------------- */
__global__ void qrope_split_kernel(const float* __restrict__ qf, const float* __restrict__ cs,
                                   const float* __restrict__ sn,
                                   bf16* __restrict__ oh, bf16* __restrict__ op)
{
    int idx = blockIdx.x * blockDim.x + threadIdx.x;
    const int total4 = B_ * H_ * S_ * (DQK_ / 4);
    if (idx >= total4) return;
    int d4 = idx % (DQK_ / 4);
    int t = idx / (DQK_ / 4);
    int s = t % S_; t /= S_;
    int h = t % H_;
    int b = t / H_;
    int d = d4 * 4;
    const float* src = qf + (((long long)(b * S_ + s)) * H_ + h) * DQK_;
    float4 val;
    if (d < DN_) {
        val = *reinterpret_cast<const float4*>(src + d);
    } else {
        int p = d - DN_;
        float4 x = *reinterpret_cast<const float4*>(src + DN_ + p);
        float4 other;
        if (p < DR_ / 2) {
            float4 o = *reinterpret_cast<const float4*>(src + DN_ + p + DR_ / 2);
            other = make_float4(-o.x, -o.y, -o.z, -o.w);
        } else {
            other = *reinterpret_cast<const float4*>(src + DN_ + p - DR_ / 2);
        }
        long long co = ((long long)b * S_ + s) * DR_ + p;
        float4 c = *reinterpret_cast<const float4*>(cs + co);
        float4 ss2 = *reinterpret_cast<const float4*>(sn + co);
        val.x = fmaf(x.x, c.x, other.x * ss2.x);
        val.y = fmaf(x.y, c.y, other.y * ss2.y);
        val.z = fmaf(x.z, c.z, other.z * ss2.z);
        val.w = fmaf(x.w, c.w, other.w * ss2.w);
    }
    uint2 hh, pp;
    split4p(val, hh, pp);
    reinterpret_cast<uint2*>(oh)[idx] = hh;
    reinterpret_cast<uint2*>(op)[idx] = pp;
}

/* k_pe rope; src rows have stride srcStride (k_pe slice of fused qkv buffer) */
__global__ void krope_kernel(const float* __restrict__ src0, int srcStride,
                             const float* __restrict__ cs,
                             const float* __restrict__ sn, float* __restrict__ kpe)
{
    int idx = blockIdx.x * blockDim.x + threadIdx.x;
    if (idx >= B_ * S_ * (DR_ / 4)) return;
    int p4 = idx % (DR_ / 4);
    int bs = idx / (DR_ / 4);
    int p = p4 * 4;
    const float* src = src0 + (long long)bs * srcStride;
    float4 x = *reinterpret_cast<const float4*>(src + p);
    float4 other;
    if (p < DR_ / 2) {
        float4 o = *reinterpret_cast<const float4*>(src + p + DR_ / 2);
        other = make_float4(-o.x, -o.y, -o.z, -o.w);
    } else {
        other = *reinterpret_cast<const float4*>(src + p - DR_ / 2);
    }
    long long co = (long long)bs * DR_ + p;
    float4 c = *reinterpret_cast<const float4*>(cs + co);
    float4 ss2 = *reinterpret_cast<const float4*>(sn + co);
    float4 val;
    val.x = fmaf(x.x, c.x, other.x * ss2.x);
    val.y = fmaf(x.y, c.y, other.y * ss2.y);
    val.z = fmaf(x.z, c.z, other.z * ss2.z);
    val.w = fmaf(x.w, c.w, other.w * ss2.w);
    *reinterpret_cast<float4*>(kpe + co) = val;
}

__global__ void kbuild_split_kernel(const float* __restrict__ kvflat, const float* __restrict__ kpe,
                                    bf16* __restrict__ oh, bf16* __restrict__ op)
{
    int idx = blockIdx.x * blockDim.x + threadIdx.x;
    const int total4 = B_ * H_ * S_ * (DQK_ / 4);
    if (idx >= total4) return;
    int d4 = idx % (DQK_ / 4);
    int t = idx / (DQK_ / 4);
    int s = t % S_; t /= S_;
    int h = t % H_;
    int b = t / H_;
    int d = d4 * 4;
    float4 val;
    if (d < DN_)
        val = *reinterpret_cast<const float4*>(
            kvflat + (((long long)(b * S_ + s)) * H_ + h) * (DN_ + DV_) + d);
    else
        val = *reinterpret_cast<const float4*>(
            kpe + ((long long)b * S_ + s) * DR_ + (d - DN_));
    uint2 hh, pp;
    split4p(val, hh, pp);
    reinterpret_cast<uint2*>(oh)[idx] = hh;
    reinterpret_cast<uint2*>(op)[idx] = pp;
}

/* v transpose -> vT h/p [b,h,d,s] */
__global__ void vbuildT_split_kernel(const float* __restrict__ kvflat,
                                     bf16* __restrict__ oh, bf16* __restrict__ op)
{
    __shared__ float t[32][33];
    int bh = blockIdx.z;
    int b = bh >> 4, h = bh & 15;
    int s0 = blockIdx.x * 32, d0 = blockIdx.y * 32;
    int x = threadIdx.x, y = threadIdx.y;
    const float* src = kvflat + ((long long)b * S_ * H_ + h) * (DN_ + DV_) + DN_;
    #pragma unroll
    for (int i = 0; i < 32; i += 8) {
        int s = s0 + y + i, d = d0 + x;
        t[y + i][x] = src[(long long)s * (H_ * (DN_ + DV_)) + d];
    }
    __syncthreads();
    long long base = ((long long)bh * DV_) * S_;
    #pragma unroll
    for (int i = 0; i < 32; i += 8) {
        int d = d0 + y + i, s = s0 + x;
        bf16 hb, pb;
        splitsc(t[x][y + i], hb, pb);
        oh[base + (long long)d * S_ + s] = hb;
        op[base + (long long)d * S_ + s] = pb;
    }
}

/* -- causal softmax, vectorized: bf162 loads/stores, float2/float4 stores --- */
__global__ __launch_bounds__(256) void softmax_kernel(float* __restrict__ wts,
                                                      bf16* __restrict__ wh,
                                                      bf16* __restrict__ wp)
{
    long long row = blockIdx.x;
    int i = (int)(row % S_);
    float* r = wts + row * (long long)S_;
    bf16* rh = wh + row * (long long)S_;
    bf16* rp = wp + row * (long long)S_;
    const __nv_bfloat162* rh2 = reinterpret_cast<const __nv_bfloat162*>(rh);
    const __nv_bfloat162* rp2 = reinterpret_cast<const __nv_bfloat162*>(rp);
    int tid = threadIdx.x;
    int nvalid = i + 1;
    int nv2 = nvalid >> 1;
    bool odd = (nvalid & 1) != 0;
    int oddOwner = nv2 & 255;

    float e[8];
    float eodd = 0.0f;
    float mx = -1e30f;
    int cnt = 0;
    for (int j2 = tid; j2 < nv2; j2 += 256) {
        __nv_bfloat162 hv = rh2[j2];
        __nv_bfloat162 pv = rp2[j2];
        float h0 = __bfloat162float(hv.x), h1 = __bfloat162float(hv.y);
        float p0 = __bfloat162float(pv.x), p1 = __bfloat162float(pv.y);
        float e0 = fmaf(p0 - h0, CINV_, h0);
        float e1 = fmaf(p1 - h1, CINV_, h1);
        e[cnt++] = e0; e[cnt++] = e1;
        mx = fmaxf(mx, fmaxf(e0, e1));
    }
    if (odd && tid == oddOwner) {
        float hv = __bfloat162float(rh[nvalid - 1]);
        float pv = __bfloat162float(rp[nvalid - 1]);
        eodd = fmaf(pv - hv, CINV_, hv);
        mx = fmaxf(mx, eodd);
    }

    __shared__ float sm[8];
    #pragma unroll
    for (int o = 16; o; o >>= 1) mx = fmaxf(mx, __shfl_xor_sync(0xffffffffu, mx, o));
    if ((tid & 31) == 0) sm[tid >> 5] = mx;
    __syncthreads();
    if (tid < 32) {
        float v = (tid < 8) ? sm[tid] : -1e30f;
        #pragma unroll
        for (int o = 4; o; o >>= 1) v = fmaxf(v, __shfl_xor_sync(0xffffffffu, v, o));
        if (tid == 0) sm[0] = v;
    }
    __syncthreads();
    mx = sm[0];
    __syncthreads();

    float sum = 0.0f;
    cnt = 0;
    for (int j2 = tid; j2 < nv2; j2 += 256) {
        float e0 = fast_exp(e[cnt] - mx); e[cnt] = e0; cnt++;
        float e1 = fast_exp(e[cnt] - mx); e[cnt] = e1; cnt++;
        sum += e0 + e1;
    }
    if (odd && tid == oddOwner) { eodd = fast_exp(eodd - mx); sum += eodd; }
    #pragma unroll
    for (int o = 16; o; o >>= 1) sum += __shfl_xor_sync(0xffffffffu, sum, o);
    if ((tid & 31) == 0) sm[tid >> 5] = sum;
    __syncthreads();
    if (tid < 32) {
        float v = (tid < 8) ? sm[tid] : 0.0f;
        #pragma unroll
        for (int o = 4; o; o >>= 1) v += __shfl_xor_sync(0xffffffffu, v, o);
        if (tid == 0) sm[0] = v;
    }
    __syncthreads();
    float inv = 1.0f / sm[0];

    cnt = 0;
    for (int j2 = tid; j2 < nv2; j2 += 256) {
        float v0 = e[cnt++] * inv;
        float v1 = e[cnt++] * inv;
        reinterpret_cast<float2*>(r)[j2] = make_float2(v0, v1);
        bf16 h0, p0, h1, p1;
        splitsc(v0, h0, p0); splitsc(v1, h1, p1);
        __nv_bfloat162 hv; hv.x = h0; hv.y = h1;
        __nv_bfloat162 pv; pv.x = p0; pv.y = p1;
        reinterpret_cast<__nv_bfloat162*>(rh)[j2] = hv;
        reinterpret_cast<__nv_bfloat162*>(rp)[j2] = pv;
    }
    if (odd && tid == oddOwner) {
        float v = eodd * inv;
        r[nvalid - 1] = v;
        bf16 hb, pb;
        splitsc(v, hb, pb);
        rh[nvalid - 1] = hb;
        rp[nvalid - 1] = pb;
    }

    /* h/p zeros up to 128-aligned bound */
    int bound = ((i >> 7) + 1) << 7;
    bf16 z = __float2bfloat16(0.0f);
    int zh0 = nvalid;
    if (zh0 & 1) {
        if (tid == 0 && zh0 < bound) { rh[zh0] = z; rp[zh0] = z; }
        zh0++;
    }
    __nv_bfloat162 z2; z2.x = z; z2.y = z;
    for (int j2 = (zh0 >> 1) + tid; j2 < (bound >> 1); j2 += 256) {
        reinterpret_cast<__nv_bfloat162*>(rh)[j2] = z2;
        reinterpret_cast<__nv_bfloat162*>(rp)[j2] = z2;
    }
    /* fp32 zeros over full masked region */
    int z4s = (nvalid + 3) & ~3;
    for (int j = nvalid + tid; j < z4s && j < S_; j += 256) r[j] = 0.0f;
    float4 zf4 = make_float4(0.f, 0.f, 0.f, 0.f);
    for (int j4 = (z4s >> 2) + tid; j4 < (S_ >> 2); j4 += 256)
        reinterpret_cast<float4*>(r)[j4] = zf4;
}

/* ---------------- host ------------------------------------------------------ */
static inline void mma_gemm(const bf16* Ah, const bf16* Ap, const bf16* Bh, const bf16* Bp,
                            float* Cf, bf16* Ch, bf16* Cp,
                            int M, int N, int K, int lda, int ldb, int ldc,
                            long long sA, long long sB,
                            int zdiv, long long csOut, long long csIn,
                            float alpha, int causalSkip, int causalK, int batch)
{
    dim3 grid((N + 63) / 64, (M + 127) / 128, batch);
    mma_gemm9_kernel<<<grid, 256, GEMM_SMEM>>>(Ah, Ap, Bh, Bp, Cf, Ch, Cp,
                                               M, N, K, lda, ldb, ldc,
                                               sA, sB, zdiv, csOut, csIn,
                                               alpha, causalSkip, causalK);
}

extern "C" void kernel_launch(void* const* d_in, const int* in_sizes, int n_in,
                              void* d_out, int out_size)
{
    const float* hs      = (const float*)d_in[0];
    const float* cs      = (const float*)d_in[1];
    const float* sn      = (const float*)d_in[2];
    const float* q_a_w   = (const float*)d_in[4];
    const float* q_a_ln  = (const float*)d_in[5];
    const float* q_b_w   = (const float*)d_in[6];
    const float* kv_a_w  = (const float*)d_in[7];
    const float* kv_a_ln = (const float*)d_in[8];
    const float* kv_b_w  = (const float*)d_in[9];
    const float* o_w     = (const float*)d_in[10];

    float* out = (float*)d_out;
    float* wts = out + (long long)B_ * S_ * HID_;

    static bool attr_set = false;
    if (!attr_set) {
        cudaFuncSetAttribute(mma_gemm9_kernel, cudaFuncAttributeMaxDynamicSharedMemorySize, GEMM_SMEM);
        attr_set = true;
    }

#define GETSYM(p, s) cudaGetSymbolAddress((void**)&p, s)
    bf16 *hsh, *hsp, *qlnh, *qlnp, *qfh, *qfp, *kch, *kcp, *kfh, *kfp, *vth, *vtp;
    bf16 *whh, *whp, *omh, *omp;
    bf16 *wqkvh, *wqkvp, *wqbh, *wqbp, *wkbh, *wkbp, *woh, *wop;
    float *qkvlat, *qflat, *kpe, *kvflat;
    GETSYM(hsh, g_hs_h);    GETSYM(hsp, g_hs_p);
    GETSYM(qkvlat, g_qkvlat);
    GETSYM(qlnh, g_qlatn_h);  GETSYM(qlnp, g_qlatn_p);
    GETSYM(qflat, g_qflat); GETSYM(qfh, g_qfull_h);   GETSYM(qfp, g_qfull_p);
    GETSYM(kch, g_kc_h);    GETSYM(kcp, g_kc_p);
    GETSYM(kpe, g_kpe);     GETSYM(kvflat, g_kvflat);
    GETSYM(kfh, g_kfull_h); GETSYM(kfp, g_kfull_p);
    GETSYM(vth, g_vT_h);    GETSYM(vtp, g_vT_p);
    GETSYM(whh, g_w_h);     GETSYM(whp, g_w_p);
    GETSYM(omh, g_omid_h);  GETSYM(omp, g_omid_p);
    GETSYM(wqkvh, g_wqkvT_h); GETSYM(wqkvp, g_wqkvT_p);
    GETSYM(wqbh, g_wqbT_h); GETSYM(wqbp, g_wqbT_p);
    GETSYM(wkbh, g_wkvbT_h); GETSYM(wkbp, g_wkvbT_p);
    GETSYM(woh, g_woT_h);   GETSYM(wop, g_woT_p);
#undef GETSYM

    dim3 tb(32, 8);
    /* 0: q_a_w -> rows [0,1536) of fused wqkvT */
    transpose_split_kernel<<<dim3(QLORA_ / 32, HID_ / 32), tb>>>(q_a_w, wqkvh, wqkvp, HID_, QLORA_);
    /* 1: kv_a_w -> rows [1536,2112) */
    transpose_split_kernel<<<dim3((KVLORA_ + DR_) / 32, HID_ / 32), tb>>>(
        kv_a_w, wqkvh + (long long)QLORA_ * HID_, wqkvp + (long long)QLORA_ * HID_,
        HID_, KVLORA_ + DR_);
    /* 2: split hidden states */
    split_kernel<<<(NTOK_ * HID_ / 4 + 255) / 256, 256>>>(hs, hsh, hsp, NTOK_ * HID_ / 4);
    /* 3: fused q_a + kv_a GEMM (profiled) -> qkvlat [4096, 2112] */
    mma_gemm(hsh, hsp, wqkvh, wqkvp, qkvlat, 0, 0,
             NTOK_, QKVN_, HID_, HID_, HID_, QKVN_,
             0, 0, 1, 0, 0, 1.0f, 0, 0, 1);
    /* 4: rms norm q latent */
    rmsnorm_split_kernel<<<NTOK_, 256>>>(qkvlat, q_a_ln, qlnh, qlnp, QLORA_, QKVN_, QLORA_);
    /* 5: rms norm kv latent */
    rmsnorm_split_kernel<<<NTOK_, 256>>>(qkvlat + QLORA_, kv_a_ln, kch, kcp, KVLORA_, QKVN_, KVLORA_);
    /* 6: k_pe rope from fused buffer */
    krope_kernel<<<(B_ * S_ * (DR_ / 4) + 255) / 256, 256>>>(
        qkvlat + QLORA_ + KVLORA_, QKVN_, cs, sn, kpe);
    /* 7 */ transpose_split_kernel<<<dim3(H_ * DQK_ / 32, QLORA_ / 32), tb>>>(q_b_w, wqbh, wqbp, QLORA_, H_ * DQK_);
    /* 8: q_b */
    mma_gemm(qlnh, qlnp, wqbh, wqbp, qflat, 0, 0,
             NTOK_, H_ * DQK_, QLORA_, QLORA_, QLORA_, H_ * DQK_,
             0, 0, 1, 0, 0, 1.0f, 0, 0, 1);
    /* 9 */ qrope_split_kernel<<<(B_ * H_ * S_ * (DQK_ / 4) + 255) / 256, 256>>>(qflat, cs, sn, qfh, qfp);
    /* 10 */ transpose_split_kernel<<<dim3(H_ * (DN_ + DV_) / 32, KVLORA_ / 32), tb>>>(kv_b_w, wkbh, wkbp, KVLORA_, H_ * (DN_ + DV_));
    /* 11: kv_b */
    mma_gemm(kch, kcp, wkbh, wkbp, kvflat, 0, 0,
             NTOK_, H_ * (DN_ + DV_), KVLORA_, KVLORA_, KVLORA_, H_ * (DN_ + DV_),
             0, 0, 1, 0, 0, 1.0f, 0, 0, 1);
    /* 12 */ kbuild_split_kernel<<<(B_ * H_ * S_ * (DQK_ / 4) + 255) / 256, 256>>>(kvflat, kpe, kfh, kfp);
    /* 13 */ vbuildT_split_kernel<<<dim3(S_ / 32, DV_ / 32, B_ * H_), tb>>>(kvflat, vth, vtp);
    /* 14: scores -> h/p logits */
    mma_gemm(qfh, qfp, kfh, kfp, 0, whh, whp,
             S_, S_, DQK_, DQK_, DQK_, S_,
             (long long)S_ * DQK_, (long long)S_ * DQK_,
             1, (long long)S_ * S_, 0,
             SCALING_, 1, 0, B_ * H_);
    /* 15: softmax */
    softmax_kernel<<<B_ * H_ * S_, 256>>>(wts, whh, whp);
    /* 16: PV -> omid h/p */
    mma_gemm(whh, whp, vth, vtp, 0, omh, omp,
             S_, DV_, S_, S_, S_, H_ * DV_,
             (long long)S_ * S_, (long long)DV_ * S_,
             H_, (long long)S_ * H_ * DV_, (long long)DV_,
             1.0f, 0, 1, B_ * H_);
    /* 17 */ transpose_split_kernel<<<dim3(HID_ / 32, (H_ * DV_) / 32), tb>>>(o_w, woh, wop, H_ * DV_, HID_);
    /* 18: o_proj */
    mma_gemm(omh, omp, woh, wop, out, 0, 0,
             NTOK_, HID_, H_ * DV_, H_ * DV_, H_ * DV_, HID_,
             0, 0, 1, 0, 0, 1.0f, 0, 0, 1);
}

// round 15
// speedup vs baseline: 1.1458x; 1.0227x over previous
#include <cuda_runtime.h>
#include <cuda_bf16.h>
#include <math.h>
#include <stdint.h>

#define B_      2
#define S_      2048
#define HID_    2048
#define H_      16
#define QLORA_  1536
#define KVLORA_ 512
#define DR_     64
#define DN_     128
#define DQK_    192
#define DV_     128
#define NTOK_   (B_*S_)
#define QKVN_   (QLORA_+KVLORA_+DR_)   /* 2112 */
#define SCALING_ 0.07216878364870322f
#define CSCALE_ 16.0f
#define CINV_   0.0625f

typedef __nv_bfloat16 bf16;

/* scratch: "h" = bf16(x), "p" = bf16(h + 16*(x-h)) */
__device__ bf16  g_hs_h [NTOK_*HID_];
__device__ bf16  g_hs_p [NTOK_*HID_];
__device__ float g_qkvlat[NTOK_*QKVN_];
__device__ bf16  g_qlatn_h[NTOK_*QLORA_];
__device__ bf16  g_qlatn_p[NTOK_*QLORA_];
__device__ float g_qflat [NTOK_*H_*DQK_];
__device__ bf16  g_qfull_h[B_*H_*S_*DQK_];
__device__ bf16  g_qfull_p[B_*H_*S_*DQK_];
__device__ bf16  g_kc_h [NTOK_*KVLORA_];
__device__ bf16  g_kc_p [NTOK_*KVLORA_];
__device__ float g_kpe   [B_*S_*DR_];
__device__ float g_kvflat[NTOK_*H_*(DN_+DV_)];
__device__ bf16  g_kfull_h[B_*H_*S_*DQK_];
__device__ bf16  g_kfull_p[B_*H_*S_*DQK_];
__device__ bf16  g_vT_h [B_*H_*DV_*S_];
__device__ bf16  g_vT_p [B_*H_*DV_*S_];
__device__ bf16  g_w_h  [(long long)B_*H_*S_*S_];
__device__ bf16  g_w_p  [(long long)B_*H_*S_*S_];
__device__ bf16  g_omid_h[NTOK_*H_*DV_];
__device__ bf16  g_omid_p[NTOK_*H_*DV_];
__device__ bf16  g_wqkvT_h[QKVN_*HID_];
__device__ bf16  g_wqkvT_p[QKVN_*HID_];
__device__ bf16  g_wqbT_h [H_*DQK_*QLORA_];
__device__ bf16  g_wqbT_p [H_*DQK_*QLORA_];
__device__ bf16  g_wkvbT_h[H_*(DN_+DV_)*KVLORA_];
__device__ bf16  g_wkvbT_p[H_*(DN_+DV_)*KVLORA_];
__device__ bf16  g_woT_h  [HID_*H_*DV_];
__device__ bf16  g_woT_p  [HID_*H_*DV_];

/* --------------------------- helpers --------------------------------------- */
__device__ __forceinline__ uint32_t smem_u32(const void* p) {
    uint32_t a;
    asm("{ .reg .u64 t; cvta.to.shared.u64 t, %1; cvt.u32.u64 %0, t; }" : "=r"(a) : "l"(p));
    return a;
}
__device__ __forceinline__ void ldsm_x4(uint32_t& r0, uint32_t& r1, uint32_t& r2, uint32_t& r3,
                                        uint32_t addr) {
    asm volatile("ldmatrix.sync.aligned.m8n8.x4.shared.b16 {%0,%1,%2,%3}, [%4];"
                 : "=r"(r0), "=r"(r1), "=r"(r2), "=r"(r3) : "r"(addr));
}
__device__ __forceinline__ void mma16816(float* c, const uint32_t* a, uint32_t b0, uint32_t b1) {
    asm volatile("mma.sync.aligned.m16n8k16.row.col.f32.bf16.bf16.f32 "
                 "{%0,%1,%2,%3}, {%4,%5,%6,%7}, {%8,%9}, {%0,%1,%2,%3};"
                 : "+f"(c[0]), "+f"(c[1]), "+f"(c[2]), "+f"(c[3])
                 : "r"(a[0]), "r"(a[1]), "r"(a[2]), "r"(a[3]), "r"(b0), "r"(b1));
}
__device__ __forceinline__ void cpa16(uint32_t dst, const void* src) {
    asm volatile("cp.async.cg.shared.global [%0], [%1], 16;"
                 :: "r"(dst), "l"(src) : "memory");
}
#define CP_COMMIT() asm volatile("cp.async.commit_group;" ::: "memory")
#define CP_WAIT1()  asm volatile("cp.async.wait_group 1;" ::: "memory")

__device__ __forceinline__ void split4p(float4 v, uint2& hh, uint2& pp) {
    float f[4] = {v.x, v.y, v.z, v.w};
    unsigned short h[4], p[4];
    #pragma unroll
    for (int i = 0; i < 4; i++) {
        bf16 hb = __float2bfloat16(f[i]);
        float hf = __bfloat162float(hb);
        bf16 pb = __float2bfloat16(fmaf(CSCALE_, f[i] - hf, hf));
        h[i] = *(unsigned short*)&hb;
        p[i] = *(unsigned short*)&pb;
    }
    hh.x = (uint32_t)h[0] | ((uint32_t)h[1] << 16);
    hh.y = (uint32_t)h[2] | ((uint32_t)h[3] << 16);
    pp.x = (uint32_t)p[0] | ((uint32_t)p[1] << 16);
    pp.y = (uint32_t)p[2] | ((uint32_t)p[3] << 16);
}
__device__ __forceinline__ void splitsc(float v, bf16& hb, bf16& pb) {
    hb = __float2bfloat16(v);
    float hf = __bfloat162float(hb);
    pb = __float2bfloat16(fmaf(CSCALE_, v - hf, hf));
}

/* FFMA-only exp */
__device__ __forceinline__ float fast_exp(float x) {
    float t = x * 1.4426950408889634f;
    float r = rintf(t);
    float f = t - r;
    float p =          1.339887440266574e-3f;
    p = fmaf(p, f,     9.618437357674640e-3f);
    p = fmaf(p, f,     5.550332471162809e-2f);
    p = fmaf(p, f,     2.402264791363012e-1f);
    p = fmaf(p, f,     6.931472028550421e-1f);
    p = fmaf(p, f,     1.0f);
    int ri = (int)r;
    if (ri < -126) ri = -126;
    float s = __int_as_float((uint32_t)(ri + 127) << 23);
    return p * s;
}

/* smem: K-chunk 64. A tiles 128x64 bf16, B 64x64; rows padded to 144B. */
#define ROWB   144
#define AH_O   0
#define AP_O   18432
#define BH_O   36864
#define BP_O   46080
#define STGSZ  55296
#define NSTG   2
#define GEMM_SMEM (NSTG*STGSZ)

/* -- bf16 HMMA GEMM: 128x64 CTA, 4 warps of 64x32, K-chunk 64, 2 CTAs/SM,
   2-pass scaled compensation C = P + (Q-P)/16; 12 LDSM -> 32 MMA per ks --- */
__global__ __launch_bounds__(128, 2) void mma_gemm11_kernel(
    const bf16* __restrict__ Ah_, const bf16* __restrict__ Ap_,
    const bf16* __restrict__ Bh_, const bf16* __restrict__ Bp_,
    float* __restrict__ Cf, bf16* __restrict__ Ch, bf16* __restrict__ Cp,
    int M, int N, int K, int lda, int ldb, int ldc,
    long long sA, long long sB, int zdiv, long long csOut, long long csIn,
    float alpha, int causalSkip, int causalK)
{
    const int row0 = blockIdx.y * 128;
    const int col0 = blockIdx.x * 64;
    if (causalSkip && col0 > row0 + 127) return;
    const int bz = blockIdx.z;
    const bf16* Ah = Ah_ + (long long)bz * sA;
    const bf16* Ap = Ap_ + (long long)bz * sA;
    const bf16* Bh = Bh_ + (long long)bz * sB;
    const bf16* Bp = Bp_ + (long long)bz * sB;
    const long long coff = (long long)(bz / zdiv) * csOut + (long long)(bz % zdiv) * csIn;

    extern __shared__ __align__(16) char smem[];
    const uint32_t sb = smem_u32(smem);

    const int tid  = threadIdx.x;
    const int wid  = tid >> 5;
    const int lane = tid & 31;
    const int wm = wid & 1;          /* M strip: rows wm*64..+64 */
    const int wn = wid >> 1;         /* N strip: cols wn*32..+32 */
    const int laneIn = lane & 7;
    const int quad   = lane >> 3;
    const int kofs   = wid & 3;

    const uint32_t aBase = (uint32_t)((wm * 64 + laneIn + (quad & 1) * 8) * ROWB
                                      + ((quad >> 1) * 8) * 2);
    const uint32_t bBase = (uint32_t)((wn * 32 + laneIn + (quad >> 1) * 8) * ROWB
                                      + ((quad & 1) * 8) * 2);

    int kend = K;
    if (causalK) { int kl = row0 + 128; if (kl < kend) kend = kl; }
    const int nch = kend >> 6;

    float accP[4][4][4], accQ[4][4][4];
    #pragma unroll
    for (int i = 0; i < 4; i++)
        #pragma unroll
        for (int j = 0; j < 4; j++)
            #pragma unroll
            for (int q = 0; q < 4; q++) { accP[i][j][q] = 0.0f; accQ[i][j][q] = 0.0f; }

    auto issue = [&](int s) {
        const uint32_t dst = sb + (uint32_t)(s & 1) * STGSZ;
        const int k0 = s << 6;
        /* A: 128 rows x 8 segs of 16B = 1024 ops per operand, 8/thread */
        #pragma unroll
        for (int i = 0; i < 8; i++) {
            const int g = tid + i * 128;
            const int r = g >> 3, sg = g & 7;
            const uint32_t so = (uint32_t)(r * ROWB + sg * 16);
            const long long ga = (long long)(row0 + r) * lda + k0 + sg * 8;
            cpa16(dst + AH_O + so, Ah + ga);
            cpa16(dst + AP_O + so, Ap + ga);
        }
        /* B: 64 rows x 8 segs = 512 ops per operand, 4/thread */
        #pragma unroll
        for (int i = 0; i < 4; i++) {
            const int g = tid + i * 128;
            const int r = g >> 3, sg = g & 7;
            const uint32_t so = (uint32_t)(r * ROWB + sg * 16);
            const long long gb = (long long)(col0 + r) * ldb + k0 + sg * 8;
            cpa16(dst + BH_O + so, Bh + gb);
            cpa16(dst + BP_O + so, Bp + gb);
        }
    };

    issue(0);
    CP_COMMIT();

    for (int c = 0; c < nch; c++) {
        if (c + 1 < nch) issue(c + 1);
        CP_COMMIT();
        CP_WAIT1();
        __syncthreads();

        const uint32_t bufb = sb + (uint32_t)(c & 1) * STGSZ;
        #pragma unroll
        for (int ks = 0; ks < 4; ks++) {
            const int ksx = (ks + kofs) & 3;
            const uint32_t kb = (uint32_t)(ksx * 32);
            uint32_t bh[2][4], bp[2][4];
            #pragma unroll
            for (int np = 0; np < 2; np++) {
                const uint32_t bo = bBase + (uint32_t)(np * 16 * ROWB) + kb;
                ldsm_x4(bh[np][0], bh[np][1], bh[np][2], bh[np][3], bufb + BH_O + bo);
                ldsm_x4(bp[np][0], bp[np][1], bp[np][2], bp[np][3], bufb + BP_O + bo);
            }
            #pragma unroll
            for (int mt = 0; mt < 4; mt++) {
                uint32_t ah[4], ap[4];
                const uint32_t ao = aBase + (uint32_t)(mt * 16 * ROWB) + kb;
                ldsm_x4(ah[0], ah[1], ah[2], ah[3], bufb + AH_O + ao);
                ldsm_x4(ap[0], ap[1], ap[2], ap[3], bufb + AP_O + ao);
                #pragma unroll
                for (int nt = 0; nt < 4; nt++)
                    mma16816(accP[mt][nt], ah,
                             bh[nt >> 1][(nt & 1) * 2], bh[nt >> 1][(nt & 1) * 2 + 1]);
                #pragma unroll
                for (int nt = 0; nt < 4; nt++)
                    mma16816(accQ[mt][nt], ap,
                             bp[nt >> 1][(nt & 1) * 2], bp[nt >> 1][(nt & 1) * 2 + 1]);
            }
        }
        __syncthreads();
    }

    const int lr  = lane >> 2;
    const int lc2 = (lane & 3) * 2;
    #pragma unroll
    for (int mt = 0; mt < 4; mt++) {
        #pragma unroll
        for (int nt = 0; nt < 4; nt++) {
            const int gr = row0 + wm * 64 + mt * 16 + lr;
            const int gc = col0 + wn * 32 + nt * 8 + lc2;
            float vv[4];
            #pragma unroll
            for (int q = 0; q < 4; q++)
                vv[q] = fmaf(accQ[mt][nt][q] - accP[mt][nt][q], CINV_, accP[mt][nt][q]) * alpha;
            const long long o0 = coff + (long long)gr * ldc + gc;
            const long long o1 = coff + (long long)(gr + 8) * ldc + gc;
            if (Cf) {
                *reinterpret_cast<float2*>(Cf + o0) = make_float2(vv[0], vv[1]);
                *reinterpret_cast<float2*>(Cf + o1) = make_float2(vv[2], vv[3]);
            }
            if (Ch) {
                bf16 h0, p0, h1, p1, h2, p2, h3, p3;
                splitsc(vv[0], h0, p0); splitsc(vv[1], h1, p1);
                splitsc(vv[2], h2, p2); splitsc(vv[3], h3, p3);
                __nv_bfloat162 hv0; hv0.x = h0; hv0.y = h1;
                __nv_bfloat162 hv1; hv1.x = h2; hv1.y = h3;
                __nv_bfloat162 pv0; pv0.x = p0; pv0.y = p1;
                __nv_bfloat162 pv1; pv1.x = p2; pv1.y = p3;
                *reinterpret_cast<__nv_bfloat162*>(Ch + o0) = hv0;
                *reinterpret_cast<__nv_bfloat162*>(Ch + o1) = hv1;
                *reinterpret_cast<__nv_bfloat162*>(Cp + o0) = pv0;
                *reinterpret_cast<__nv_bfloat162*>(Cp + o1) = pv1;
            }
        }
    }
}

/* ---------------- split fp32 -> h/p bf16 ------------------------------------ */
__global__ void split_kernel(const float* __restrict__ x, bf16* __restrict__ h,
                             bf16* __restrict__ p, int n4)
{
    int idx = blockIdx.x * blockDim.x + threadIdx.x;
    if (idx >= n4) return;
    float4 v = reinterpret_cast<const float4*>(x)[idx];
    uint2 hh, pp;
    split4p(v, hh, pp);
    reinterpret_cast<uint2*>(h)[idx] = hh;
    reinterpret_cast<uint2*>(p)[idx] = pp;
}

/* ---------------- transpose [K,N] fp32 -> [N,K] h/p bf16 -------------------- */
__global__ void transpose_split_kernel(const float* __restrict__ in,
                                       bf16* __restrict__ outH, bf16* __restrict__ outP,
                                       int K, int N)
{
    __shared__ float t[32][33];
    int k0 = blockIdx.y * 32, n0 = blockIdx.x * 32;
    int x = threadIdx.x, y = threadIdx.y;
    #pragma unroll
    for (int i = 0; i < 32; i += 8) {
        int k = k0 + y + i, n = n0 + x;
        t[y + i][x] = (k < K && n < N) ? in[(long long)k * N + n] : 0.0f;
    }
    __syncthreads();
    #pragma unroll
    for (int i = 0; i < 32; i += 8) {
        int n = n0 + y + i, k = k0 + x;
        if (n < N && k < K) {
            bf16 hb, pb;
            splitsc(t[x][y + i], hb, pb);
            outH[(long long)n * K + k] = hb;
            outP[(long long)n * K + k] = pb;
        }
    }
}

/* ---------------- RMS norm -> h/p ------------------------------------------- */
__global__ __launch_bounds__(256) void rmsnorm_split_kernel(
    const float* __restrict__ x, const float* __restrict__ w,
    bf16* __restrict__ yh, bf16* __restrict__ yp, int n, int ldx, int ldy)
{
    int row = blockIdx.x;
    const float* xr = x + (long long)row * ldx;
    int tid = threadIdx.x;
    float ss = 0.0f;
    for (int i = tid; i < n; i += 256) { float v = xr[i]; ss += v * v; }
    __shared__ float red[8];
    #pragma unroll
    for (int o = 16; o; o >>= 1) ss += __shfl_xor_sync(0xffffffffu, ss, o);
    if ((tid & 31) == 0) red[tid >> 5] = ss;
    __syncthreads();
    if (tid < 32) {
        float v = (tid < 8) ? red[tid] : 0.0f;
        #pragma unroll
        for (int o = 4; o; o >>= 1) v += __shfl_xor_sync(0xffffffffu, v, o);
        if (tid == 0) red[0] = v;
    }
    __syncthreads();
    float inv = rsqrtf(red[0] / (float)n + 1e-6f);
    bf16* yhr = yh + (long long)row * ldy;
    bf16* ypr = yp + (long long)row * ldy;
    for (int i = tid; i < n; i += 256) {
        bf16 hb, pb;
        splitsc(w[i] * xr[i] * inv, hb, pb);
        yhr[i] = hb;
        ypr[i] = pb;
    }
}

/* ---------------- q rope -> qfull h/p ---------------------------------------- */
__global__ void qrope_split_kernel(const float* __restrict__ qf, const float* __restrict__ cs,
                                   const float* __restrict__ sn,
                                   bf16* __restrict__ oh, bf16* __restrict__ op)
{
    int idx = blockIdx.x * blockDim.x + threadIdx.x;
    const int total4 = B_ * H_ * S_ * (DQK_ / 4);
    if (idx >= total4) return;
    int d4 = idx % (DQK_ / 4);
    int t = idx / (DQK_ / 4);
    int s = t % S_; t /= S_;
    int h = t % H_;
    int b = t / H_;
    int d = d4 * 4;
    const float* src = qf + (((long long)(b * S_ + s)) * H_ + h) * DQK_;
    float4 val;
    if (d < DN_) {
        val = *reinterpret_cast<const float4*>(src + d);
    } else {
        int p = d - DN_;
        float4 x = *reinterpret_cast<const float4*>(src + DN_ + p);
        float4 other;
        if (p < DR_ / 2) {
            float4 o = *reinterpret_cast<const float4*>(src + DN_ + p + DR_ / 2);
            other = make_float4(-o.x, -o.y, -o.z, -o.w);
        } else {
            other = *reinterpret_cast<const float4*>(src + DN_ + p - DR_ / 2);
        }
        long long co = ((long long)b * S_ + s) * DR_ + p;
        float4 c = *reinterpret_cast<const float4*>(cs + co);
        float4 ss2 = *reinterpret_cast<const float4*>(sn + co);
        val.x = fmaf(x.x, c.x, other.x * ss2.x);
        val.y = fmaf(x.y, c.y, other.y * ss2.y);
        val.z = fmaf(x.z, c.z, other.z * ss2.z);
        val.w = fmaf(x.w, c.w, other.w * ss2.w);
    }
    uint2 hh, pp;
    split4p(val, hh, pp);
    reinterpret_cast<uint2*>(oh)[idx] = hh;
    reinterpret_cast<uint2*>(op)[idx] = pp;
}

/* k_pe rope; src rows have stride srcStride */
__global__ void krope_kernel(const float* __restrict__ src0, int srcStride,
                             const float* __restrict__ cs,
                             const float* __restrict__ sn, float* __restrict__ kpe)
{
    int idx = blockIdx.x * blockDim.x + threadIdx.x;
    if (idx >= B_ * S_ * (DR_ / 4)) return;
    int p4 = idx % (DR_ / 4);
    int bs = idx / (DR_ / 4);
    int p = p4 * 4;
    const float* src = src0 + (long long)bs * srcStride;
    float4 x = *reinterpret_cast<const float4*>(src + p);
    float4 other;
    if (p < DR_ / 2) {
        float4 o = *reinterpret_cast<const float4*>(src + p + DR_ / 2);
        other = make_float4(-o.x, -o.y, -o.z, -o.w);
    } else {
        other = *reinterpret_cast<const float4*>(src + p - DR_ / 2);
    }
    long long co = (long long)bs * DR_ + p;
    float4 c = *reinterpret_cast<const float4*>(cs + co);
    float4 ss2 = *reinterpret_cast<const float4*>(sn + co);
    float4 val;
    val.x = fmaf(x.x, c.x, other.x * ss2.x);
    val.y = fmaf(x.y, c.y, other.y * ss2.y);
    val.z = fmaf(x.z, c.z, other.z * ss2.z);
    val.w = fmaf(x.w, c.w, other.w * ss2.w);
    *reinterpret_cast<float4*>(kpe + co) = val;
}

__global__ void kbuild_split_kernel(const float* __restrict__ kvflat, const float* __restrict__ kpe,
                                    bf16* __restrict__ oh, bf16* __restrict__ op)
{
    int idx = blockIdx.x * blockDim.x + threadIdx.x;
    const int total4 = B_ * H_ * S_ * (DQK_ / 4);
    if (idx >= total4) return;
    int d4 = idx % (DQK_ / 4);
    int t = idx / (DQK_ / 4);
    int s = t % S_; t /= S_;
    int h = t % H_;
    int b = t / H_;
    int d = d4 * 4;
    float4 val;
    if (d < DN_)
        val = *reinterpret_cast<const float4*>(
            kvflat + (((long long)(b * S_ + s)) * H_ + h) * (DN_ + DV_) + d);
    else
        val = *reinterpret_cast<const float4*>(
            kpe + ((long long)b * S_ + s) * DR_ + (d - DN_));
    uint2 hh, pp;
    split4p(val, hh, pp);
    reinterpret_cast<uint2*>(oh)[idx] = hh;
    reinterpret_cast<uint2*>(op)[idx] = pp;
}

/* v transpose -> vT h/p [b,h,d,s] */
__global__ void vbuildT_split_kernel(const float* __restrict__ kvflat,
                                     bf16* __restrict__ oh, bf16* __restrict__ op)
{
    __shared__ float t[32][33];
    int bh = blockIdx.z;
    int b = bh >> 4, h = bh & 15;
    int s0 = blockIdx.x * 32, d0 = blockIdx.y * 32;
    int x = threadIdx.x, y = threadIdx.y;
    const float* src = kvflat + ((long long)b * S_ * H_ + h) * (DN_ + DV_) + DN_;
    #pragma unroll
    for (int i = 0; i < 32; i += 8) {
        int s = s0 + y + i, d = d0 + x;
        t[y + i][x] = src[(long long)s * (H_ * (DN_ + DV_)) + d];
    }
    __syncthreads();
    long long base = ((long long)bh * DV_) * S_;
    #pragma unroll
    for (int i = 0; i < 32; i += 8) {
        int d = d0 + y + i, s = s0 + x;
        bf16 hb, pb;
        splitsc(t[x][y + i], hb, pb);
        oh[base + (long long)d * S_ + s] = hb;
        op[base + (long long)d * S_ + s] = pb;
    }
}

/* -- causal softmax, vectorized -------------------------------------------- */
__global__ __launch_bounds__(256) void softmax_kernel(float* __restrict__ wts,
                                                      bf16* __restrict__ wh,
                                                      bf16* __restrict__ wp)
{
    long long row = blockIdx.x;
    int i = (int)(row % S_);
    float* r = wts + row * (long long)S_;
    bf16* rh = wh + row * (long long)S_;
    bf16* rp = wp + row * (long long)S_;
    const __nv_bfloat162* rh2 = reinterpret_cast<const __nv_bfloat162*>(rh);
    const __nv_bfloat162* rp2 = reinterpret_cast<const __nv_bfloat162*>(rp);
    int tid = threadIdx.x;
    int nvalid = i + 1;
    int nv2 = nvalid >> 1;
    bool odd = (nvalid & 1) != 0;
    int oddOwner = nv2 & 255;

    float e[8];
    float eodd = 0.0f;
    float mx = -1e30f;
    int cnt = 0;
    for (int j2 = tid; j2 < nv2; j2 += 256) {
        __nv_bfloat162 hv = rh2[j2];
        __nv_bfloat162 pv = rp2[j2];
        float h0 = __bfloat162float(hv.x), h1 = __bfloat162float(hv.y);
        float p0 = __bfloat162float(pv.x), p1 = __bfloat162float(pv.y);
        float e0 = fmaf(p0 - h0, CINV_, h0);
        float e1 = fmaf(p1 - h1, CINV_, h1);
        e[cnt++] = e0; e[cnt++] = e1;
        mx = fmaxf(mx, fmaxf(e0, e1));
    }
    if (odd && tid == oddOwner) {
        float hv = __bfloat162float(rh[nvalid - 1]);
        float pv = __bfloat162float(rp[nvalid - 1]);
        eodd = fmaf(pv - hv, CINV_, hv);
        mx = fmaxf(mx, eodd);
    }

    __shared__ float sm[8];
    #pragma unroll
    for (int o = 16; o; o >>= 1) mx = fmaxf(mx, __shfl_xor_sync(0xffffffffu, mx, o));
    if ((tid & 31) == 0) sm[tid >> 5] = mx;
    __syncthreads();
    if (tid < 32) {
        float v = (tid < 8) ? sm[tid] : -1e30f;
        #pragma unroll
        for (int o = 4; o; o >>= 1) v = fmaxf(v, __shfl_xor_sync(0xffffffffu, v, o));
        if (tid == 0) sm[0] = v;
    }
    __syncthreads();
    mx = sm[0];
    __syncthreads();

    float sum = 0.0f;
    cnt = 0;
    for (int j2 = tid; j2 < nv2; j2 += 256) {
        float e0 = fast_exp(e[cnt] - mx); e[cnt] = e0; cnt++;
        float e1 = fast_exp(e[cnt] - mx); e[cnt] = e1; cnt++;
        sum += e0 + e1;
    }
    if (odd && tid == oddOwner) { eodd = fast_exp(eodd - mx); sum += eodd; }
    #pragma unroll
    for (int o = 16; o; o >>= 1) sum += __shfl_xor_sync(0xffffffffu, sum, o);
    if ((tid & 31) == 0) sm[tid >> 5] = sum;
    __syncthreads();
    if (tid < 32) {
        float v = (tid < 8) ? sm[tid] : 0.0f;
        #pragma unroll
        for (int o = 4; o; o >>= 1) v += __shfl_xor_sync(0xffffffffu, v, o);
        if (tid == 0) sm[0] = v;
    }
    __syncthreads();
    float inv = 1.0f / sm[0];

    cnt = 0;
    for (int j2 = tid; j2 < nv2; j2 += 256) {
        float v0 = e[cnt++] * inv;
        float v1 = e[cnt++] * inv;
        reinterpret_cast<float2*>(r)[j2] = make_float2(v0, v1);
        bf16 h0, p0, h1, p1;
        splitsc(v0, h0, p0); splitsc(v1, h1, p1);
        __nv_bfloat162 hv; hv.x = h0; hv.y = h1;
        __nv_bfloat162 pv; pv.x = p0; pv.y = p1;
        reinterpret_cast<__nv_bfloat162*>(rh)[j2] = hv;
        reinterpret_cast<__nv_bfloat162*>(rp)[j2] = pv;
    }
    if (odd && tid == oddOwner) {
        float v = eodd * inv;
        r[nvalid - 1] = v;
        bf16 hb, pb;
        splitsc(v, hb, pb);
        rh[nvalid - 1] = hb;
        rp[nvalid - 1] = pb;
    }

    int bound = ((i >> 7) + 1) << 7;
    bf16 z = __float2bfloat16(0.0f);
    int zh0 = nvalid;
    if (zh0 & 1) {
        if (tid == 0 && zh0 < bound) { rh[zh0] = z; rp[zh0] = z; }
        zh0++;
    }
    __nv_bfloat162 z2; z2.x = z; z2.y = z;
    for (int j2 = (zh0 >> 1) + tid; j2 < (bound >> 1); j2 += 256) {
        reinterpret_cast<__nv_bfloat162*>(rh)[j2] = z2;
        reinterpret_cast<__nv_bfloat162*>(rp)[j2] = z2;
    }
    int z4s = (nvalid + 3) & ~3;
    for (int j = nvalid + tid; j < z4s && j < S_; j += 256) r[j] = 0.0f;
    float4 zf4 = make_float4(0.f, 0.f, 0.f, 0.f);
    for (int j4 = (z4s >> 2) + tid; j4 < (S_ >> 2); j4 += 256)
        reinterpret_cast<float4*>(r)[j4] = zf4;
}

/* ---------------- host ------------------------------------------------------ */
static inline void mma_gemm(const bf16* Ah, const bf16* Ap, const bf16* Bh, const bf16* Bp,
                            float* Cf, bf16* Ch, bf16* Cp,
                            int M, int N, int K, int lda, int ldb, int ldc,
                            long long sA, long long sB,
                            int zdiv, long long csOut, long long csIn,
                            float alpha, int causalSkip, int causalK, int batch)
{
    dim3 grid((N + 63) / 64, (M + 127) / 128, batch);
    mma_gemm11_kernel<<<grid, 128, GEMM_SMEM>>>(Ah, Ap, Bh, Bp, Cf, Ch, Cp,
                                                M, N, K, lda, ldb, ldc,
                                                sA, sB, zdiv, csOut, csIn,
                                                alpha, causalSkip, causalK);
}

extern "C" void kernel_launch(void* const* d_in, const int* in_sizes, int n_in,
                              void* d_out, int out_size)
{
    const float* hs      = (const float*)d_in[0];
    const float* cs      = (const float*)d_in[1];
    const float* sn      = (const float*)d_in[2];
    const float* q_a_w   = (const float*)d_in[4];
    const float* q_a_ln  = (const float*)d_in[5];
    const float* q_b_w   = (const float*)d_in[6];
    const float* kv_a_w  = (const float*)d_in[7];
    const float* kv_a_ln = (const float*)d_in[8];
    const float* kv_b_w  = (const float*)d_in[9];
    const float* o_w     = (const float*)d_in[10];

    float* out = (float*)d_out;
    float* wts = out + (long long)B_ * S_ * HID_;

    static bool attr_set = false;
    if (!attr_set) {
        cudaFuncSetAttribute(mma_gemm11_kernel, cudaFuncAttributeMaxDynamicSharedMemorySize, GEMM_SMEM);
        attr_set = true;
    }

#define GETSYM(p, s) cudaGetSymbolAddress((void**)&p, s)
    bf16 *hsh, *hsp, *qlnh, *qlnp, *qfh, *qfp, *kch, *kcp, *kfh, *kfp, *vth, *vtp;
    bf16 *whh, *whp, *omh, *omp;
    bf16 *wqkvh, *wqkvp, *wqbh, *wqbp, *wkbh, *wkbp, *woh, *wop;
    float *qkvlat, *qflat, *kpe, *kvflat;
    GETSYM(hsh, g_hs_h);    GETSYM(hsp, g_hs_p);
    GETSYM(qkvlat, g_qkvlat);
    GETSYM(qlnh, g_qlatn_h);  GETSYM(qlnp, g_qlatn_p);
    GETSYM(qflat, g_qflat); GETSYM(qfh, g_qfull_h);   GETSYM(qfp, g_qfull_p);
    GETSYM(kch, g_kc_h);    GETSYM(kcp, g_kc_p);
    GETSYM(kpe, g_kpe);     GETSYM(kvflat, g_kvflat);
    GETSYM(kfh, g_kfull_h); GETSYM(kfp, g_kfull_p);
    GETSYM(vth, g_vT_h);    GETSYM(vtp, g_vT_p);
    GETSYM(whh, g_w_h);     GETSYM(whp, g_w_p);
    GETSYM(omh, g_omid_h);  GETSYM(omp, g_omid_p);
    GETSYM(wqkvh, g_wqkvT_h); GETSYM(wqkvp, g_wqkvT_p);
    GETSYM(wqbh, g_wqbT_h); GETSYM(wqbp, g_wqbT_p);
    GETSYM(wkbh, g_wkvbT_h); GETSYM(wkbp, g_wkvbT_p);
    GETSYM(woh, g_woT_h);   GETSYM(wop, g_woT_p);
#undef GETSYM

    dim3 tb(32, 8);
    /* 0: q_a_w -> rows [0,1536) of fused wqkvT */
    transpose_split_kernel<<<dim3(QLORA_ / 32, HID_ / 32), tb>>>(q_a_w, wqkvh, wqkvp, HID_, QLORA_);
    /* 1: kv_a_w -> rows [1536,2112) */
    transpose_split_kernel<<<dim3((KVLORA_ + DR_) / 32, HID_ / 32), tb>>>(
        kv_a_w, wqkvh + (long long)QLORA_ * HID_, wqkvp + (long long)QLORA_ * HID_,
        HID_, KVLORA_ + DR_);
    /* 2: split hidden states */
    split_kernel<<<(NTOK_ * HID_ / 4 + 255) / 256, 256>>>(hs, hsh, hsp, NTOK_ * HID_ / 4);
    /* 3: fused q_a + kv_a GEMM (profiled) */
    mma_gemm(hsh, hsp, wqkvh, wqkvp, qkvlat, 0, 0,
             NTOK_, QKVN_, HID_, HID_, HID_, QKVN_,
             0, 0, 1, 0, 0, 1.0f, 0, 0, 1);
    /* 4: rms norm q latent */
    rmsnorm_split_kernel<<<NTOK_, 256>>>(qkvlat, q_a_ln, qlnh, qlnp, QLORA_, QKVN_, QLORA_);
    /* 5: rms norm kv latent */
    rmsnorm_split_kernel<<<NTOK_, 256>>>(qkvlat + QLORA_, kv_a_ln, kch, kcp, KVLORA_, QKVN_, KVLORA_);
    /* 6: k_pe rope */
    krope_kernel<<<(B_ * S_ * (DR_ / 4) + 255) / 256, 256>>>(
        qkvlat + QLORA_ + KVLORA_, QKVN_, cs, sn, kpe);
    /* 7 */ transpose_split_kernel<<<dim3(H_ * DQK_ / 32, QLORA_ / 32), tb>>>(q_b_w, wqbh, wqbp, QLORA_, H_ * DQK_);
    /* 8: q_b */
    mma_gemm(qlnh, qlnp, wqbh, wqbp, qflat, 0, 0,
             NTOK_, H_ * DQK_, QLORA_, QLORA_, QLORA_, H_ * DQK_,
             0, 0, 1, 0, 0, 1.0f, 0, 0, 1);
    /* 9 */ qrope_split_kernel<<<(B_ * H_ * S_ * (DQK_ / 4) + 255) / 256, 256>>>(qflat, cs, sn, qfh, qfp);
    /* 10 */ transpose_split_kernel<<<dim3(H_ * (DN_ + DV_) / 32, KVLORA_ / 32), tb>>>(kv_b_w, wkbh, wkbp, KVLORA_, H_ * (DN_ + DV_));
    /* 11: kv_b */
    mma_gemm(kch, kcp, wkbh, wkbp, kvflat, 0, 0,
             NTOK_, H_ * (DN_ + DV_), KVLORA_, KVLORA_, KVLORA_, H_ * (DN_ + DV_),
             0, 0, 1, 0, 0, 1.0f, 0, 0, 1);
    /* 12 */ kbuild_split_kernel<<<(B_ * H_ * S_ * (DQK_ / 4) + 255) / 256, 256>>>(kvflat, kpe, kfh, kfp);
    /* 13 */ vbuildT_split_kernel<<<dim3(S_ / 32, DV_ / 32, B_ * H_), tb>>>(kvflat, vth, vtp);
    /* 14: scores -> h/p logits */
    mma_gemm(qfh, qfp, kfh, kfp, 0, whh, whp,
             S_, S_, DQK_, DQK_, DQK_, S_,
             (long long)S_ * DQK_, (long long)S_ * DQK_,
             1, (long long)S_ * S_, 0,
             SCALING_, 1, 0, B_ * H_);
    /* 15: softmax */
    softmax_kernel<<<B_ * H_ * S_, 256>>>(wts, whh, whp);
    /* 16: PV -> omid h/p */
    mma_gemm(whh, whp, vth, vtp, 0, omh, omp,
             S_, DV_, S_, S_, S_, H_ * DV_,
             (long long)S_ * S_, (long long)DV_ * S_,
             H_, (long long)S_ * H_ * DV_, (long long)DV_,
             1.0f, 0, 1, B_ * H_);
    /* 17 */ transpose_split_kernel<<<dim3(HID_ / 32, (H_ * DV_) / 32), tb>>>(o_w, woh, wop, H_ * DV_, HID_);
    /* 18: o_proj */
    mma_gemm(omh, omp, woh, wop, out, 0, 0,
             NTOK_, HID_, H_ * DV_, H_ * DV_, H_ * DV_, HID_,
             0, 0, 1, 0, 0, 1.0f, 0, 0, 1);
}

// round 16
// speedup vs baseline: 1.1781x; 1.0282x over previous
#include <cuda_runtime.h>
#include <cuda_bf16.h>
#include <math.h>
#include <stdint.h>

#define B_      2
#define S_      2048
#define HID_    2048
#define H_      16
#define QLORA_  1536
#define KVLORA_ 512
#define DR_     64
#define DN_     128
#define DQK_    192
#define DV_     128
#define NTOK_   (B_*S_)
#define QKVN_   (QLORA_+KVLORA_+DR_)   /* 2112 */
#define SCALING_ 0.07216878364870322f
#define CSCALE_ 16.0f
#define CINV_   0.0625f

typedef __nv_bfloat16 bf16;

/* scratch: "h" = bf16(x), "p" = bf16(h + 16*(x-h)) */
__device__ bf16  g_hs_h [NTOK_*HID_];
__device__ bf16  g_hs_p [NTOK_*HID_];
__device__ float g_qkvlat[NTOK_*QKVN_];
__device__ bf16  g_qlatn_h[NTOK_*QLORA_];
__device__ bf16  g_qlatn_p[NTOK_*QLORA_];
__device__ float g_qflat [NTOK_*H_*DQK_];
__device__ bf16  g_qfull_h[B_*H_*S_*DQK_];
__device__ bf16  g_qfull_p[B_*H_*S_*DQK_];
__device__ bf16  g_kc_h [NTOK_*KVLORA_];
__device__ bf16  g_kc_p [NTOK_*KVLORA_];
__device__ float g_kpe   [B_*S_*DR_];
__device__ float g_kvflat[NTOK_*H_*(DN_+DV_)];
__device__ bf16  g_kfull_h[B_*H_*S_*DQK_];
__device__ bf16  g_kfull_p[B_*H_*S_*DQK_];
__device__ bf16  g_vT_h [B_*H_*DV_*S_];
__device__ bf16  g_vT_p [B_*H_*DV_*S_];
__device__ bf16  g_w_h  [(long long)B_*H_*S_*S_];
__device__ bf16  g_w_p  [(long long)B_*H_*S_*S_];
__device__ bf16  g_omid_h[NTOK_*H_*DV_];
__device__ bf16  g_omid_p[NTOK_*H_*DV_];
__device__ bf16  g_wqkvT_h[QKVN_*HID_];
__device__ bf16  g_wqkvT_p[QKVN_*HID_];
__device__ bf16  g_wqbT_h [H_*DQK_*QLORA_];
__device__ bf16  g_wqbT_p [H_*DQK_*QLORA_];
__device__ bf16  g_wkvbT_h[H_*(DN_+DV_)*KVLORA_];
__device__ bf16  g_wkvbT_p[H_*(DN_+DV_)*KVLORA_];
__device__ bf16  g_woT_h  [HID_*H_*DV_];
__device__ bf16  g_woT_p  [HID_*H_*DV_];

/* --------------------------- helpers --------------------------------------- */
__device__ __forceinline__ uint32_t smem_u32(const void* p) {
    uint32_t a;
    asm("{ .reg .u64 t; cvta.to.shared.u64 t, %1; cvt.u32.u64 %0, t; }" : "=r"(a) : "l"(p));
    return a;
}
__device__ __forceinline__ void ldsm_x4(uint32_t& r0, uint32_t& r1, uint32_t& r2, uint32_t& r3,
                                        uint32_t addr) {
    asm volatile("ldmatrix.sync.aligned.m8n8.x4.shared.b16 {%0,%1,%2,%3}, [%4];"
                 : "=r"(r0), "=r"(r1), "=r"(r2), "=r"(r3) : "r"(addr));
}
__device__ __forceinline__ void mma16816(float* c, const uint32_t* a, uint32_t b0, uint32_t b1) {
    asm volatile("mma.sync.aligned.m16n8k16.row.col.f32.bf16.bf16.f32 "
                 "{%0,%1,%2,%3}, {%4,%5,%6,%7}, {%8,%9}, {%0,%1,%2,%3};"
                 : "+f"(c[0]), "+f"(c[1]), "+f"(c[2]), "+f"(c[3])
                 : "r"(a[0]), "r"(a[1]), "r"(a[2]), "r"(a[3]), "r"(b0), "r"(b1));
}
__device__ __forceinline__ void cpa16(uint32_t dst, const void* src) {
    asm volatile("cp.async.cg.shared.global [%0], [%1], 16;"
                 :: "r"(dst), "l"(src) : "memory");
}
#define CP_COMMIT() asm volatile("cp.async.commit_group;" ::: "memory")
#define CP_WAIT1()  asm volatile("cp.async.wait_group 1;" ::: "memory")

__device__ __forceinline__ void split4p(float4 v, uint2& hh, uint2& pp) {
    float f[4] = {v.x, v.y, v.z, v.w};
    unsigned short h[4], p[4];
    #pragma unroll
    for (int i = 0; i < 4; i++) {
        bf16 hb = __float2bfloat16(f[i]);
        float hf = __bfloat162float(hb);
        bf16 pb = __float2bfloat16(fmaf(CSCALE_, f[i] - hf, hf));
        h[i] = *(unsigned short*)&hb;
        p[i] = *(unsigned short*)&pb;
    }
    hh.x = (uint32_t)h[0] | ((uint32_t)h[1] << 16);
    hh.y = (uint32_t)h[2] | ((uint32_t)h[3] << 16);
    pp.x = (uint32_t)p[0] | ((uint32_t)p[1] << 16);
    pp.y = (uint32_t)p[2] | ((uint32_t)p[3] << 16);
}
__device__ __forceinline__ void splitsc(float v, bf16& hb, bf16& pb) {
    hb = __float2bfloat16(v);
    float hf = __bfloat162float(hb);
    pb = __float2bfloat16(fmaf(CSCALE_, v - hf, hf));
}

/* FFMA-only exp */
__device__ __forceinline__ float fast_exp(float x) {
    float t = x * 1.4426950408889634f;
    float r = rintf(t);
    float f = t - r;
    float p =          1.339887440266574e-3f;
    p = fmaf(p, f,     9.618437357674640e-3f);
    p = fmaf(p, f,     5.550332471162809e-2f);
    p = fmaf(p, f,     2.402264791363012e-1f);
    p = fmaf(p, f,     6.931472028550421e-1f);
    p = fmaf(p, f,     1.0f);
    int ri = (int)r;
    if (ri < -126) ri = -126;
    float s = __int_as_float((uint32_t)(ri + 127) << 23);
    return p * s;
}

/* smem: K-chunk 64. A tiles 128x64 bf16, B 64x64; rows padded to 144B. */
#define ROWB   144
#define AH_O   0
#define AP_O   18432
#define BH_O   36864
#define BP_O   46080
#define STGSZ  55296
#define NSTG   2
#define GEMM_SMEM (NSTG*STGSZ)

/* -- bf16 HMMA GEMM: 128x64 CTA, 4 warps of 64x32, K-chunk 64, 2 CTAs/SM,
   2-pass scaled compensation C = P + (Q-P)/16; 12 LDSM -> 32 MMA per ks --- */
__global__ __launch_bounds__(128, 2) void mma_gemm11_kernel(
    const bf16* __restrict__ Ah_, const bf16* __restrict__ Ap_,
    const bf16* __restrict__ Bh_, const bf16* __restrict__ Bp_,
    float* __restrict__ Cf, bf16* __restrict__ Ch, bf16* __restrict__ Cp,
    int M, int N, int K, int lda, int ldb, int ldc,
    long long sA, long long sB, int zdiv, long long csOut, long long csIn,
    float alpha, int causalSkip, int causalK)
{
    const int row0 = blockIdx.y * 128;
    const int col0 = blockIdx.x * 64;
    if (causalSkip && col0 > row0 + 127) return;
    const int bz = blockIdx.z;
    const bf16* Ah = Ah_ + (long long)bz * sA;
    const bf16* Ap = Ap_ + (long long)bz * sA;
    const bf16* Bh = Bh_ + (long long)bz * sB;
    const bf16* Bp = Bp_ + (long long)bz * sB;
    const long long coff = (long long)(bz / zdiv) * csOut + (long long)(bz % zdiv) * csIn;

    extern __shared__ __align__(16) char smem[];
    const uint32_t sb = smem_u32(smem);

    const int tid  = threadIdx.x;
    const int wid  = tid >> 5;
    const int lane = tid & 31;
    const int wm = wid & 1;
    const int wn = wid >> 1;
    const int laneIn = lane & 7;
    const int quad   = lane >> 3;
    const int kofs   = wid & 3;

    const uint32_t aBase = (uint32_t)((wm * 64 + laneIn + (quad & 1) * 8) * ROWB
                                      + ((quad >> 1) * 8) * 2);
    const uint32_t bBase = (uint32_t)((wn * 32 + laneIn + (quad >> 1) * 8) * ROWB
                                      + ((quad & 1) * 8) * 2);

    int kend = K;
    if (causalK) { int kl = row0 + 128; if (kl < kend) kend = kl; }
    const int nch = kend >> 6;

    float accP[4][4][4], accQ[4][4][4];
    #pragma unroll
    for (int i = 0; i < 4; i++)
        #pragma unroll
        for (int j = 0; j < 4; j++)
            #pragma unroll
            for (int q = 0; q < 4; q++) { accP[i][j][q] = 0.0f; accQ[i][j][q] = 0.0f; }

    auto issue = [&](int s) {
        const uint32_t dst = sb + (uint32_t)(s & 1) * STGSZ;
        const int k0 = s << 6;
        #pragma unroll
        for (int i = 0; i < 8; i++) {
            const int g = tid + i * 128;
            const int r = g >> 3, sg = g & 7;
            const uint32_t so = (uint32_t)(r * ROWB + sg * 16);
            const long long ga = (long long)(row0 + r) * lda + k0 + sg * 8;
            cpa16(dst + AH_O + so, Ah + ga);
            cpa16(dst + AP_O + so, Ap + ga);
        }
        #pragma unroll
        for (int i = 0; i < 4; i++) {
            const int g = tid + i * 128;
            const int r = g >> 3, sg = g & 7;
            const uint32_t so = (uint32_t)(r * ROWB + sg * 16);
            const long long gb = (long long)(col0 + r) * ldb + k0 + sg * 8;
            cpa16(dst + BH_O + so, Bh + gb);
            cpa16(dst + BP_O + so, Bp + gb);
        }
    };

    issue(0);
    CP_COMMIT();

    for (int c = 0; c < nch; c++) {
        if (c + 1 < nch) issue(c + 1);
        CP_COMMIT();
        CP_WAIT1();
        __syncthreads();

        const uint32_t bufb = sb + (uint32_t)(c & 1) * STGSZ;
        #pragma unroll
        for (int ks = 0; ks < 4; ks++) {
            const int ksx = (ks + kofs) & 3;
            const uint32_t kb = (uint32_t)(ksx * 32);
            uint32_t bh[2][4], bp[2][4];
            #pragma unroll
            for (int np = 0; np < 2; np++) {
                const uint32_t bo = bBase + (uint32_t)(np * 16 * ROWB) + kb;
                ldsm_x4(bh[np][0], bh[np][1], bh[np][2], bh[np][3], bufb + BH_O + bo);
                ldsm_x4(bp[np][0], bp[np][1], bp[np][2], bp[np][3], bufb + BP_O + bo);
            }
            #pragma unroll
            for (int mt = 0; mt < 4; mt++) {
                uint32_t ah[4], ap[4];
                const uint32_t ao = aBase + (uint32_t)(mt * 16 * ROWB) + kb;
                ldsm_x4(ah[0], ah[1], ah[2], ah[3], bufb + AH_O + ao);
                ldsm_x4(ap[0], ap[1], ap[2], ap[3], bufb + AP_O + ao);
                #pragma unroll
                for (int nt = 0; nt < 4; nt++)
                    mma16816(accP[mt][nt], ah,
                             bh[nt >> 1][(nt & 1) * 2], bh[nt >> 1][(nt & 1) * 2 + 1]);
                #pragma unroll
                for (int nt = 0; nt < 4; nt++)
                    mma16816(accQ[mt][nt], ap,
                             bp[nt >> 1][(nt & 1) * 2], bp[nt >> 1][(nt & 1) * 2 + 1]);
            }
        }
        __syncthreads();
    }

    const int lr  = lane >> 2;
    const int lc2 = (lane & 3) * 2;
    #pragma unroll
    for (int mt = 0; mt < 4; mt++) {
        #pragma unroll
        for (int nt = 0; nt < 4; nt++) {
            const int gr = row0 + wm * 64 + mt * 16 + lr;
            const int gc = col0 + wn * 32 + nt * 8 + lc2;
            float vv[4];
            #pragma unroll
            for (int q = 0; q < 4; q++)
                vv[q] = fmaf(accQ[mt][nt][q] - accP[mt][nt][q], CINV_, accP[mt][nt][q]) * alpha;
            const long long o0 = coff + (long long)gr * ldc + gc;
            const long long o1 = coff + (long long)(gr + 8) * ldc + gc;
            if (Cf) {
                *reinterpret_cast<float2*>(Cf + o0) = make_float2(vv[0], vv[1]);
                *reinterpret_cast<float2*>(Cf + o1) = make_float2(vv[2], vv[3]);
            }
            if (Ch) {
                bf16 h0, p0, h1, p1, h2, p2, h3, p3;
                splitsc(vv[0], h0, p0); splitsc(vv[1], h1, p1);
                splitsc(vv[2], h2, p2); splitsc(vv[3], h3, p3);
                __nv_bfloat162 hv0; hv0.x = h0; hv0.y = h1;
                __nv_bfloat162 hv1; hv1.x = h2; hv1.y = h3;
                __nv_bfloat162 pv0; pv0.x = p0; pv0.y = p1;
                __nv_bfloat162 pv1; pv1.x = p2; pv1.y = p3;
                *reinterpret_cast<__nv_bfloat162*>(Ch + o0) = hv0;
                *reinterpret_cast<__nv_bfloat162*>(Ch + o1) = hv1;
                *reinterpret_cast<__nv_bfloat162*>(Cp + o0) = pv0;
                *reinterpret_cast<__nv_bfloat162*>(Cp + o1) = pv1;
            }
        }
    }
}

/* ---------------- split fp32 -> h/p bf16 ------------------------------------ */
__global__ void split_kernel(const float* __restrict__ x, bf16* __restrict__ h,
                             bf16* __restrict__ p, int n4)
{
    int idx = blockIdx.x * blockDim.x + threadIdx.x;
    if (idx >= n4) return;
    float4 v = reinterpret_cast<const float4*>(x)[idx];
    uint2 hh, pp;
    split4p(v, hh, pp);
    reinterpret_cast<uint2*>(h)[idx] = hh;
    reinterpret_cast<uint2*>(p)[idx] = pp;
}

/* ---------------- transpose [K,N] fp32 -> [N,K] h/p bf16 -------------------- */
__global__ void transpose_split_kernel(const float* __restrict__ in,
                                       bf16* __restrict__ outH, bf16* __restrict__ outP,
                                       int K, int N)
{
    __shared__ float t[32][33];
    int k0 = blockIdx.y * 32, n0 = blockIdx.x * 32;
    int x = threadIdx.x, y = threadIdx.y;
    #pragma unroll
    for (int i = 0; i < 32; i += 8) {
        int k = k0 + y + i, n = n0 + x;
        t[y + i][x] = (k < K && n < N) ? in[(long long)k * N + n] : 0.0f;
    }
    __syncthreads();
    #pragma unroll
    for (int i = 0; i < 32; i += 8) {
        int n = n0 + y + i, k = k0 + x;
        if (n < N && k < K) {
            bf16 hb, pb;
            splitsc(t[x][y + i], hb, pb);
            outH[(long long)n * K + k] = hb;
            outP[(long long)n * K + k] = pb;
        }
    }
}

/* ---------------- RMS norm -> h/p ------------------------------------------- */
__global__ __launch_bounds__(256) void rmsnorm_split_kernel(
    const float* __restrict__ x, const float* __restrict__ w,
    bf16* __restrict__ yh, bf16* __restrict__ yp, int n, int ldx, int ldy)
{
    int row = blockIdx.x;
    const float* xr = x + (long long)row * ldx;
    int tid = threadIdx.x;
    float ss = 0.0f;
    for (int i = tid; i < n; i += 256) { float v = xr[i]; ss += v * v; }
    __shared__ float red[8];
    #pragma unroll
    for (int o = 16; o; o >>= 1) ss += __shfl_xor_sync(0xffffffffu, ss, o);
    if ((tid & 31) == 0) red[tid >> 5] = ss;
    __syncthreads();
    if (tid < 32) {
        float v = (tid < 8) ? red[tid] : 0.0f;
        #pragma unroll
        for (int o = 4; o; o >>= 1) v += __shfl_xor_sync(0xffffffffu, v, o);
        if (tid == 0) red[0] = v;
    }
    __syncthreads();
    float inv = rsqrtf(red[0] / (float)n + 1e-6f);
    bf16* yhr = yh + (long long)row * ldy;
    bf16* ypr = yp + (long long)row * ldy;
    for (int i = tid; i < n; i += 256) {
        bf16 hb, pb;
        splitsc(w[i] * xr[i] * inv, hb, pb);
        yhr[i] = hb;
        ypr[i] = pb;
    }
}

/* ---------------- q rope -> qfull h/p ---------------------------------------- */
__global__ void qrope_split_kernel(const float* __restrict__ qf, const float* __restrict__ cs,
                                   const float* __restrict__ sn,
                                   bf16* __restrict__ oh, bf16* __restrict__ op)
{
    int idx = blockIdx.x * blockDim.x + threadIdx.x;
    const int total4 = B_ * H_ * S_ * (DQK_ / 4);
    if (idx >= total4) return;
    int d4 = idx % (DQK_ / 4);
    int t = idx / (DQK_ / 4);
    int s = t % S_; t /= S_;
    int h = t % H_;
    int b = t / H_;
    int d = d4 * 4;
    const float* src = qf + (((long long)(b * S_ + s)) * H_ + h) * DQK_;
    float4 val;
    if (d < DN_) {
        val = *reinterpret_cast<const float4*>(src + d);
    } else {
        int p = d - DN_;
        float4 x = *reinterpret_cast<const float4*>(src + DN_ + p);
        float4 other;
        if (p < DR_ / 2) {
            float4 o = *reinterpret_cast<const float4*>(src + DN_ + p + DR_ / 2);
            other = make_float4(-o.x, -o.y, -o.z, -o.w);
        } else {
            other = *reinterpret_cast<const float4*>(src + DN_ + p - DR_ / 2);
        }
        long long co = ((long long)b * S_ + s) * DR_ + p;
        float4 c = *reinterpret_cast<const float4*>(cs + co);
        float4 ss2 = *reinterpret_cast<const float4*>(sn + co);
        val.x = fmaf(x.x, c.x, other.x * ss2.x);
        val.y = fmaf(x.y, c.y, other.y * ss2.y);
        val.z = fmaf(x.z, c.z, other.z * ss2.z);
        val.w = fmaf(x.w, c.w, other.w * ss2.w);
    }
    uint2 hh, pp;
    split4p(val, hh, pp);
    reinterpret_cast<uint2*>(oh)[idx] = hh;
    reinterpret_cast<uint2*>(op)[idx] = pp;
}

/* k_pe rope; src rows have stride srcStride */
__global__ void krope_kernel(const float* __restrict__ src0, int srcStride,
                             const float* __restrict__ cs,
                             const float* __restrict__ sn, float* __restrict__ kpe)
{
    int idx = blockIdx.x * blockDim.x + threadIdx.x;
    if (idx >= B_ * S_ * (DR_ / 4)) return;
    int p4 = idx % (DR_ / 4);
    int bs = idx / (DR_ / 4);
    int p = p4 * 4;
    const float* src = src0 + (long long)bs * srcStride;
    float4 x = *reinterpret_cast<const float4*>(src + p);
    float4 other;
    if (p < DR_ / 2) {
        float4 o = *reinterpret_cast<const float4*>(src + p + DR_ / 2);
        other = make_float4(-o.x, -o.y, -o.z, -o.w);
    } else {
        other = *reinterpret_cast<const float4*>(src + p - DR_ / 2);
    }
    long long co = (long long)bs * DR_ + p;
    float4 c = *reinterpret_cast<const float4*>(cs + co);
    float4 ss2 = *reinterpret_cast<const float4*>(sn + co);
    float4 val;
    val.x = fmaf(x.x, c.x, other.x * ss2.x);
    val.y = fmaf(x.y, c.y, other.y * ss2.y);
    val.z = fmaf(x.z, c.z, other.z * ss2.z);
    val.w = fmaf(x.w, c.w, other.w * ss2.w);
    *reinterpret_cast<float4*>(kpe + co) = val;
}

__global__ void kbuild_split_kernel(const float* __restrict__ kvflat, const float* __restrict__ kpe,
                                    bf16* __restrict__ oh, bf16* __restrict__ op)
{
    int idx = blockIdx.x * blockDim.x + threadIdx.x;
    const int total4 = B_ * H_ * S_ * (DQK_ / 4);
    if (idx >= total4) return;
    int d4 = idx % (DQK_ / 4);
    int t = idx / (DQK_ / 4);
    int s = t % S_; t /= S_;
    int h = t % H_;
    int b = t / H_;
    int d = d4 * 4;
    float4 val;
    if (d < DN_)
        val = *reinterpret_cast<const float4*>(
            kvflat + (((long long)(b * S_ + s)) * H_ + h) * (DN_ + DV_) + d);
    else
        val = *reinterpret_cast<const float4*>(
            kpe + ((long long)b * S_ + s) * DR_ + (d - DN_));
    uint2 hh, pp;
    split4p(val, hh, pp);
    reinterpret_cast<uint2*>(oh)[idx] = hh;
    reinterpret_cast<uint2*>(op)[idx] = pp;
}

/* v transpose -> vT h/p [b,h,d,s] */
__global__ void vbuildT_split_kernel(const float* __restrict__ kvflat,
                                     bf16* __restrict__ oh, bf16* __restrict__ op)
{
    __shared__ float t[32][33];
    int bh = blockIdx.z;
    int b = bh >> 4, h = bh & 15;
    int s0 = blockIdx.x * 32, d0 = blockIdx.y * 32;
    int x = threadIdx.x, y = threadIdx.y;
    const float* src = kvflat + ((long long)b * S_ * H_ + h) * (DN_ + DV_) + DN_;
    #pragma unroll
    for (int i = 0; i < 32; i += 8) {
        int s = s0 + y + i, d = d0 + x;
        t[y + i][x] = src[(long long)s * (H_ * (DN_ + DV_)) + d];
    }
    __syncthreads();
    long long base = ((long long)bh * DV_) * S_;
    #pragma unroll
    for (int i = 0; i < 32; i += 8) {
        int d = d0 + y + i, s = s0 + x;
        bf16 hb, pb;
        splitsc(t[x][y + i], hb, pb);
        oh[base + (long long)d * S_ + s] = hb;
        op[base + (long long)d * S_ + s] = pb;
    }
}

/* -- causal softmax, vectorized -------------------------------------------- */
__global__ __launch_bounds__(256) void softmax_kernel(float* __restrict__ wts,
                                                      bf16* __restrict__ wh,
                                                      bf16* __restrict__ wp)
{
    long long row = blockIdx.x;
    int i = (int)(row % S_);
    float* r = wts + row * (long long)S_;
    bf16* rh = wh + row * (long long)S_;
    bf16* rp = wp + row * (long long)S_;
    const __nv_bfloat162* rh2 = reinterpret_cast<const __nv_bfloat162*>(rh);
    const __nv_bfloat162* rp2 = reinterpret_cast<const __nv_bfloat162*>(rp);
    int tid = threadIdx.x;
    int nvalid = i + 1;
    int nv2 = nvalid >> 1;
    bool odd = (nvalid & 1) != 0;
    int oddOwner = nv2 & 255;

    float e[8];
    float eodd = 0.0f;
    float mx = -1e30f;
    int cnt = 0;
    for (int j2 = tid; j2 < nv2; j2 += 256) {
        __nv_bfloat162 hv = rh2[j2];
        __nv_bfloat162 pv = rp2[j2];
        float h0 = __bfloat162float(hv.x), h1 = __bfloat162float(hv.y);
        float p0 = __bfloat162float(pv.x), p1 = __bfloat162float(pv.y);
        float e0 = fmaf(p0 - h0, CINV_, h0);
        float e1 = fmaf(p1 - h1, CINV_, h1);
        e[cnt++] = e0; e[cnt++] = e1;
        mx = fmaxf(mx, fmaxf(e0, e1));
    }
    if (odd && tid == oddOwner) {
        float hv = __bfloat162float(rh[nvalid - 1]);
        float pv = __bfloat162float(rp[nvalid - 1]);
        eodd = fmaf(pv - hv, CINV_, hv);
        mx = fmaxf(mx, eodd);
    }

    __shared__ float sm[8];
    #pragma unroll
    for (int o = 16; o; o >>= 1) mx = fmaxf(mx, __shfl_xor_sync(0xffffffffu, mx, o));
    if ((tid & 31) == 0) sm[tid >> 5] = mx;
    __syncthreads();
    if (tid < 32) {
        float v = (tid < 8) ? sm[tid] : -1e30f;
        #pragma unroll
        for (int o = 4; o; o >>= 1) v = fmaxf(v, __shfl_xor_sync(0xffffffffu, v, o));
        if (tid == 0) sm[0] = v;
    }
    __syncthreads();
    mx = sm[0];
    __syncthreads();

    float sum = 0.0f;
    cnt = 0;
    for (int j2 = tid; j2 < nv2; j2 += 256) {
        float e0 = fast_exp(e[cnt] - mx); e[cnt] = e0; cnt++;
        float e1 = fast_exp(e[cnt] - mx); e[cnt] = e1; cnt++;
        sum += e0 + e1;
    }
    if (odd && tid == oddOwner) { eodd = fast_exp(eodd - mx); sum += eodd; }
    #pragma unroll
    for (int o = 16; o; o >>= 1) sum += __shfl_xor_sync(0xffffffffu, sum, o);
    if ((tid & 31) == 0) sm[tid >> 5] = sum;
    __syncthreads();
    if (tid < 32) {
        float v = (tid < 8) ? sm[tid] : 0.0f;
        #pragma unroll
        for (int o = 4; o; o >>= 1) v += __shfl_xor_sync(0xffffffffu, v, o);
        if (tid == 0) sm[0] = v;
    }
    __syncthreads();
    float inv = 1.0f / sm[0];

    cnt = 0;
    for (int j2 = tid; j2 < nv2; j2 += 256) {
        float v0 = e[cnt++] * inv;
        float v1 = e[cnt++] * inv;
        reinterpret_cast<float2*>(r)[j2] = make_float2(v0, v1);
        bf16 h0, p0, h1, p1;
        splitsc(v0, h0, p0); splitsc(v1, h1, p1);
        __nv_bfloat162 hv; hv.x = h0; hv.y = h1;
        __nv_bfloat162 pv; pv.x = p0; pv.y = p1;
        reinterpret_cast<__nv_bfloat162*>(rh)[j2] = hv;
        reinterpret_cast<__nv_bfloat162*>(rp)[j2] = pv;
    }
    if (odd && tid == oddOwner) {
        float v = eodd * inv;
        r[nvalid - 1] = v;
        bf16 hb, pb;
        splitsc(v, hb, pb);
        rh[nvalid - 1] = hb;
        rp[nvalid - 1] = pb;
    }

    int bound = ((i >> 7) + 1) << 7;
    bf16 z = __float2bfloat16(0.0f);
    int zh0 = nvalid;
    if (zh0 & 1) {
        if (tid == 0 && zh0 < bound) { rh[zh0] = z; rp[zh0] = z; }
        zh0++;
    }
    __nv_bfloat162 z2; z2.x = z; z2.y = z;
    for (int j2 = (zh0 >> 1) + tid; j2 < (bound >> 1); j2 += 256) {
        reinterpret_cast<__nv_bfloat162*>(rh)[j2] = z2;
        reinterpret_cast<__nv_bfloat162*>(rp)[j2] = z2;
    }
    int z4s = (nvalid + 3) & ~3;
    for (int j = nvalid + tid; j < z4s && j < S_; j += 256) r[j] = 0.0f;
    float4 zf4 = make_float4(0.f, 0.f, 0.f, 0.f);
    for (int j4 = (z4s >> 2) + tid; j4 < (S_ >> 2); j4 += 256)
        reinterpret_cast<float4*>(r)[j4] = zf4;
}

/* ---------------- host ------------------------------------------------------ */
static inline void mma_gemm_s(cudaStream_t st,
                              const bf16* Ah, const bf16* Ap, const bf16* Bh, const bf16* Bp,
                              float* Cf, bf16* Ch, bf16* Cp,
                              int M, int N, int K, int lda, int ldb, int ldc,
                              long long sA, long long sB,
                              int zdiv, long long csOut, long long csIn,
                              float alpha, int causalSkip, int causalK, int batch)
{
    dim3 grid((N + 63) / 64, (M + 127) / 128, batch);
    mma_gemm11_kernel<<<grid, 128, GEMM_SMEM, st>>>(Ah, Ap, Bh, Bp, Cf, Ch, Cp,
                                                    M, N, K, lda, ldb, ldc,
                                                    sA, sB, zdiv, csOut, csIn,
                                                    alpha, causalSkip, causalK);
}

extern "C" void kernel_launch(void* const* d_in, const int* in_sizes, int n_in,
                              void* d_out, int out_size)
{
    const float* hs      = (const float*)d_in[0];
    const float* cs      = (const float*)d_in[1];
    const float* sn      = (const float*)d_in[2];
    const float* q_a_w   = (const float*)d_in[4];
    const float* q_a_ln  = (const float*)d_in[5];
    const float* q_b_w   = (const float*)d_in[6];
    const float* kv_a_w  = (const float*)d_in[7];
    const float* kv_a_ln = (const float*)d_in[8];
    const float* kv_b_w  = (const float*)d_in[9];
    const float* o_w     = (const float*)d_in[10];

    float* out = (float*)d_out;
    float* wts = out + (long long)B_ * S_ * HID_;

    static bool init_done = false;
    static cudaStream_t s1, s2;
    static cudaEvent_t evA, evW, evG1, evKV;
    if (!init_done) {
        cudaFuncSetAttribute(mma_gemm11_kernel, cudaFuncAttributeMaxDynamicSharedMemorySize, GEMM_SMEM);
        cudaStreamCreateWithFlags(&s1, cudaStreamNonBlocking);
        cudaStreamCreateWithFlags(&s2, cudaStreamNonBlocking);
        cudaEventCreateWithFlags(&evA,  cudaEventDisableTiming);
        cudaEventCreateWithFlags(&evW,  cudaEventDisableTiming);
        cudaEventCreateWithFlags(&evG1, cudaEventDisableTiming);
        cudaEventCreateWithFlags(&evKV, cudaEventDisableTiming);
        init_done = true;
    }
    cudaStream_t s0 = 0;

#define GETSYM(p, s) cudaGetSymbolAddress((void**)&p, s)
    bf16 *hsh, *hsp, *qlnh, *qlnp, *qfh, *qfp, *kch, *kcp, *kfh, *kfp, *vth, *vtp;
    bf16 *whh, *whp, *omh, *omp;
    bf16 *wqkvh, *wqkvp, *wqbh, *wqbp, *wkbh, *wkbp, *woh, *wop;
    float *qkvlat, *qflat, *kpe, *kvflat;
    GETSYM(hsh, g_hs_h);    GETSYM(hsp, g_hs_p);
    GETSYM(qkvlat, g_qkvlat);
    GETSYM(qlnh, g_qlatn_h);  GETSYM(qlnp, g_qlatn_p);
    GETSYM(qflat, g_qflat); GETSYM(qfh, g_qfull_h);   GETSYM(qfp, g_qfull_p);
    GETSYM(kch, g_kc_h);    GETSYM(kcp, g_kc_p);
    GETSYM(kpe, g_kpe);     GETSYM(kvflat, g_kvflat);
    GETSYM(kfh, g_kfull_h); GETSYM(kfp, g_kfull_p);
    GETSYM(vth, g_vT_h);    GETSYM(vtp, g_vT_p);
    GETSYM(whh, g_w_h);     GETSYM(whp, g_w_p);
    GETSYM(omh, g_omid_h);  GETSYM(omp, g_omid_p);
    GETSYM(wqkvh, g_wqkvT_h); GETSYM(wqkvp, g_wqkvT_p);
    GETSYM(wqbh, g_wqbT_h); GETSYM(wqbp, g_wqbT_p);
    GETSYM(wkbh, g_wkvbT_h); GETSYM(wkbp, g_wkvbT_p);
    GETSYM(woh, g_woT_h);   GETSYM(wop, g_woT_p);
#undef GETSYM

    dim3 tb(32, 8);

    /* fork root (no launches yet) */
    cudaEventRecord(evA, s0);

    /* --- s0: launches 0..3 (index 3 = fused GEMM, profiled) --- */
    transpose_split_kernel<<<dim3(QLORA_ / 32, HID_ / 32), tb, 0, s0>>>(q_a_w, wqkvh, wqkvp, HID_, QLORA_);
    transpose_split_kernel<<<dim3((KVLORA_ + DR_) / 32, HID_ / 32), tb, 0, s0>>>(
        kv_a_w, wqkvh + (long long)QLORA_ * HID_, wqkvp + (long long)QLORA_ * HID_,
        HID_, KVLORA_ + DR_);
    split_kernel<<<(NTOK_ * HID_ / 4 + 255) / 256, 256, 0, s0>>>(hs, hsh, hsp, NTOK_ * HID_ / 4);
    mma_gemm_s(s0, hsh, hsp, wqkvh, wqkvp, qkvlat, 0, 0,
               NTOK_, QKVN_, HID_, HID_, HID_, QKVN_,
               0, 0, 1, 0, 0, 1.0f, 0, 0, 1);
    cudaEventRecord(evG1, s0);

    /* --- s1: independent weight transposes (overlap with fused GEMM) --- */
    cudaStreamWaitEvent(s1, evA, 0);
    transpose_split_kernel<<<dim3(H_ * DQK_ / 32, QLORA_ / 32), tb, 0, s1>>>(q_b_w, wqbh, wqbp, QLORA_, H_ * DQK_);
    transpose_split_kernel<<<dim3(H_ * (DN_ + DV_) / 32, KVLORA_ / 32), tb, 0, s1>>>(kv_b_w, wkbh, wkbp, KVLORA_, H_ * (DN_ + DV_));
    transpose_split_kernel<<<dim3(HID_ / 32, (H_ * DV_) / 32), tb, 0, s1>>>(o_w, woh, wop, H_ * DV_, HID_);
    cudaEventRecord(evW, s1);

    /* --- s2: kv track (rms_kv -> krope -> kv_b -> kbuild, vbuildT) --- */
    cudaStreamWaitEvent(s2, evG1, 0);
    cudaStreamWaitEvent(s2, evW, 0);
    rmsnorm_split_kernel<<<NTOK_, 256, 0, s2>>>(qkvlat + QLORA_, kv_a_ln, kch, kcp, KVLORA_, QKVN_, KVLORA_);
    krope_kernel<<<(B_ * S_ * (DR_ / 4) + 255) / 256, 256, 0, s2>>>(
        qkvlat + QLORA_ + KVLORA_, QKVN_, cs, sn, kpe);
    mma_gemm_s(s2, kch, kcp, wkbh, wkbp, kvflat, 0, 0,
               NTOK_, H_ * (DN_ + DV_), KVLORA_, KVLORA_, KVLORA_, H_ * (DN_ + DV_),
               0, 0, 1, 0, 0, 1.0f, 0, 0, 1);
    kbuild_split_kernel<<<(B_ * H_ * S_ * (DQK_ / 4) + 255) / 256, 256, 0, s2>>>(kvflat, kpe, kfh, kfp);
    vbuildT_split_kernel<<<dim3(S_ / 32, DV_ / 32, B_ * H_), tb, 0, s2>>>(kvflat, vth, vtp);
    cudaEventRecord(evKV, s2);

    /* --- s0: q track --- */
    rmsnorm_split_kernel<<<NTOK_, 256, 0, s0>>>(qkvlat, q_a_ln, qlnh, qlnp, QLORA_, QKVN_, QLORA_);
    cudaStreamWaitEvent(s0, evW, 0);
    mma_gemm_s(s0, qlnh, qlnp, wqbh, wqbp, qflat, 0, 0,
               NTOK_, H_ * DQK_, QLORA_, QLORA_, QLORA_, H_ * DQK_,
               0, 0, 1, 0, 0, 1.0f, 0, 0, 1);
    qrope_split_kernel<<<(B_ * H_ * S_ * (DQK_ / 4) + 255) / 256, 256, 0, s0>>>(qflat, cs, sn, qfh, qfp);

    /* join kv track, then attention */
    cudaStreamWaitEvent(s0, evKV, 0);
    mma_gemm_s(s0, qfh, qfp, kfh, kfp, 0, whh, whp,
               S_, S_, DQK_, DQK_, DQK_, S_,
               (long long)S_ * DQK_, (long long)S_ * DQK_,
               1, (long long)S_ * S_, 0,
               SCALING_, 1, 0, B_ * H_);
    softmax_kernel<<<B_ * H_ * S_, 256, 0, s0>>>(wts, whh, whp);
    mma_gemm_s(s0, whh, whp, vth, vtp, 0, omh, omp,
               S_, DV_, S_, S_, S_, H_ * DV_,
               (long long)S_ * S_, (long long)DV_ * S_,
               H_, (long long)S_ * H_ * DV_, (long long)DV_,
               1.0f, 0, 1, B_ * H_);
    mma_gemm_s(s0, omh, omp, woh, wop, out, 0, 0,
               NTOK_, HID_, H_ * DV_, H_ * DV_, H_ * DV_, HID_,
               0, 0, 1, 0, 0, 1.0f, 0, 0, 1);
}

// round 17
// speedup vs baseline: 1.1879x; 1.0083x over previous
#include <cuda_runtime.h>
#include <cuda_bf16.h>
#include <math.h>
#include <stdint.h>

#define B_      2
#define S_      2048
#define HID_    2048
#define H_      16
#define QLORA_  1536
#define KVLORA_ 512
#define DR_     64
#define DN_     128
#define DQK_    192
#define DV_     128
#define NTOK_   (B_*S_)
#define QKVN_   (QLORA_+KVLORA_+DR_)   /* 2112 */
#define SCALING_ 0.07216878364870322f
#define CSCALE_ 16.0f
#define CINV_   0.0625f

typedef __nv_bfloat16 bf16;

/* scratch: "h" = bf16(x), "p" = bf16(h + 16*(x-h)) */
__device__ bf16  g_hs_h [NTOK_*HID_];
__device__ bf16  g_hs_p [NTOK_*HID_];
__device__ float g_qkvlat[NTOK_*QKVN_];
__device__ bf16  g_qlatn_h[NTOK_*QLORA_];
__device__ bf16  g_qlatn_p[NTOK_*QLORA_];
__device__ float g_qflat [NTOK_*H_*DQK_];
__device__ bf16  g_qfull_h[B_*H_*S_*DQK_];
__device__ bf16  g_qfull_p[B_*H_*S_*DQK_];
__device__ bf16  g_kc_h [NTOK_*KVLORA_];
__device__ bf16  g_kc_p [NTOK_*KVLORA_];
__device__ float g_kpe   [B_*S_*DR_];
__device__ float g_kvflat[NTOK_*H_*(DN_+DV_)];
__device__ bf16  g_kfull_h[B_*H_*S_*DQK_];
__device__ bf16  g_kfull_p[B_*H_*S_*DQK_];
__device__ bf16  g_vT_h [B_*H_*DV_*S_];
__device__ bf16  g_vT_p [B_*H_*DV_*S_];
__device__ bf16  g_w_h  [(long long)B_*H_*S_*S_];
__device__ bf16  g_w_p  [(long long)B_*H_*S_*S_];
__device__ bf16  g_omid_h[NTOK_*H_*DV_];
__device__ bf16  g_omid_p[NTOK_*H_*DV_];
__device__ bf16  g_wqkvT_h[QKVN_*HID_];
__device__ bf16  g_wqkvT_p[QKVN_*HID_];
__device__ bf16  g_wqbT_h [H_*DQK_*QLORA_];
__device__ bf16  g_wqbT_p [H_*DQK_*QLORA_];
__device__ bf16  g_wkvbT_h[H_*(DN_+DV_)*KVLORA_];
__device__ bf16  g_wkvbT_p[H_*(DN_+DV_)*KVLORA_];
__device__ bf16  g_woT_h  [HID_*H_*DV_];
__device__ bf16  g_woT_p  [HID_*H_*DV_];

/* --------------------------- helpers --------------------------------------- */
__device__ __forceinline__ uint32_t smem_u32(const void* p) {
    uint32_t a;
    asm("{ .reg .u64 t; cvta.to.shared.u64 t, %1; cvt.u32.u64 %0, t; }" : "=r"(a) : "l"(p));
    return a;
}
__device__ __forceinline__ void ldsm_x4(uint32_t& r0, uint32_t& r1, uint32_t& r2, uint32_t& r3,
                                        uint32_t addr) {
    asm volatile("ldmatrix.sync.aligned.m8n8.x4.shared.b16 {%0,%1,%2,%3}, [%4];"
                 : "=r"(r0), "=r"(r1), "=r"(r2), "=r"(r3) : "r"(addr));
}
__device__ __forceinline__ void mma16816(float* c, const uint32_t* a, uint32_t b0, uint32_t b1) {
    asm volatile("mma.sync.aligned.m16n8k16.row.col.f32.bf16.bf16.f32 "
                 "{%0,%1,%2,%3}, {%4,%5,%6,%7}, {%8,%9}, {%0,%1,%2,%3};"
                 : "+f"(c[0]), "+f"(c[1]), "+f"(c[2]), "+f"(c[3])
                 : "r"(a[0]), "r"(a[1]), "r"(a[2]), "r"(a[3]), "r"(b0), "r"(b1));
}
__device__ __forceinline__ void cpa16(uint32_t dst, const void* src) {
    asm volatile("cp.async.cg.shared.global [%0], [%1], 16;"
                 :: "r"(dst), "l"(src) : "memory");
}
#define CP_COMMIT() asm volatile("cp.async.commit_group;" ::: "memory")
#define CP_WAIT1()  asm volatile("cp.async.wait_group 1;" ::: "memory")

__device__ __forceinline__ void split4p(float4 v, uint2& hh, uint2& pp) {
    float f[4] = {v.x, v.y, v.z, v.w};
    unsigned short h[4], p[4];
    #pragma unroll
    for (int i = 0; i < 4; i++) {
        bf16 hb = __float2bfloat16(f[i]);
        float hf = __bfloat162float(hb);
        bf16 pb = __float2bfloat16(fmaf(CSCALE_, f[i] - hf, hf));
        h[i] = *(unsigned short*)&hb;
        p[i] = *(unsigned short*)&pb;
    }
    hh.x = (uint32_t)h[0] | ((uint32_t)h[1] << 16);
    hh.y = (uint32_t)h[2] | ((uint32_t)h[3] << 16);
    pp.x = (uint32_t)p[0] | ((uint32_t)p[1] << 16);
    pp.y = (uint32_t)p[2] | ((uint32_t)p[3] << 16);
}
__device__ __forceinline__ void splitsc(float v, bf16& hb, bf16& pb) {
    hb = __float2bfloat16(v);
    float hf = __bfloat162float(hb);
    pb = __float2bfloat16(fmaf(CSCALE_, v - hf, hf));
}

/* FFMA-only exp */
__device__ __forceinline__ float fast_exp(float x) {
    float t = x * 1.4426950408889634f;
    float r = rintf(t);
    float f = t - r;
    float p =          1.339887440266574e-3f;
    p = fmaf(p, f,     9.618437357674640e-3f);
    p = fmaf(p, f,     5.550332471162809e-2f);
    p = fmaf(p, f,     2.402264791363012e-1f);
    p = fmaf(p, f,     6.931472028550421e-1f);
    p = fmaf(p, f,     1.0f);
    int ri = (int)r;
    if (ri < -126) ri = -126;
    float s = __int_as_float((uint32_t)(ri + 127) << 23);
    return p * s;
}

/* smem: K-chunk 64. A tiles 128x64 bf16, B 64x64; rows padded to 144B. */
#define ROWB   144
#define AH_O   0
#define AP_O   18432
#define BH_O   36864
#define BP_O   46080
#define STGSZ  55296
#define NSTG   2
#define GEMM_SMEM (NSTG*STGSZ)

/* -- bf16 HMMA GEMM: 128x64 CTA, 4 warps of 64x32, K-chunk 64, 2 CTAs/SM,
   2-pass scaled compensation C = P + (Q-P)/16 ------------------------------ */
__global__ __launch_bounds__(128, 2) void mma_gemm11_kernel(
    const bf16* __restrict__ Ah_, const bf16* __restrict__ Ap_,
    const bf16* __restrict__ Bh_, const bf16* __restrict__ Bp_,
    float* __restrict__ Cf, bf16* __restrict__ Ch, bf16* __restrict__ Cp,
    int M, int N, int K, int lda, int ldb, int ldc,
    long long sA, long long sB, int zdiv, long long csOut, long long csIn,
    float alpha, int causalSkip, int causalK)
{
    const int row0 = blockIdx.y * 128;
    const int col0 = blockIdx.x * 64;
    if (causalSkip && col0 > row0 + 127) return;
    const int bz = blockIdx.z;
    const bf16* Ah = Ah_ + (long long)bz * sA;
    const bf16* Ap = Ap_ + (long long)bz * sA;
    const bf16* Bh = Bh_ + (long long)bz * sB;
    const bf16* Bp = Bp_ + (long long)bz * sB;
    const long long coff = (long long)(bz / zdiv) * csOut + (long long)(bz % zdiv) * csIn;

    extern __shared__ __align__(16) char smem[];
    const uint32_t sb = smem_u32(smem);

    const int tid  = threadIdx.x;
    const int wid  = tid >> 5;
    const int lane = tid & 31;
    const int wm = wid & 1;
    const int wn = wid >> 1;
    const int laneIn = lane & 7;
    const int quad   = lane >> 3;
    const int kofs   = wid & 3;

    const uint32_t aBase = (uint32_t)((wm * 64 + laneIn + (quad & 1) * 8) * ROWB
                                      + ((quad >> 1) * 8) * 2);
    const uint32_t bBase = (uint32_t)((wn * 32 + laneIn + (quad >> 1) * 8) * ROWB
                                      + ((quad & 1) * 8) * 2);

    int kend = K;
    if (causalK) { int kl = row0 + 128; if (kl < kend) kend = kl; }
    const int nch = kend >> 6;

    float accP[4][4][4], accQ[4][4][4];
    #pragma unroll
    for (int i = 0; i < 4; i++)
        #pragma unroll
        for (int j = 0; j < 4; j++)
            #pragma unroll
            for (int q = 0; q < 4; q++) { accP[i][j][q] = 0.0f; accQ[i][j][q] = 0.0f; }

    auto issue = [&](int s) {
        const uint32_t dst = sb + (uint32_t)(s & 1) * STGSZ;
        const int k0 = s << 6;
        #pragma unroll
        for (int i = 0; i < 8; i++) {
            const int g = tid + i * 128;
            const int r = g >> 3, sg = g & 7;
            const uint32_t so = (uint32_t)(r * ROWB + sg * 16);
            const long long ga = (long long)(row0 + r) * lda + k0 + sg * 8;
            cpa16(dst + AH_O + so, Ah + ga);
            cpa16(dst + AP_O + so, Ap + ga);
        }
        #pragma unroll
        for (int i = 0; i < 4; i++) {
            const int g = tid + i * 128;
            const int r = g >> 3, sg = g & 7;
            const uint32_t so = (uint32_t)(r * ROWB + sg * 16);
            const long long gb = (long long)(col0 + r) * ldb + k0 + sg * 8;
            cpa16(dst + BH_O + so, Bh + gb);
            cpa16(dst + BP_O + so, Bp + gb);
        }
    };

    issue(0);
    CP_COMMIT();

    for (int c = 0; c < nch; c++) {
        if (c + 1 < nch) issue(c + 1);
        CP_COMMIT();
        CP_WAIT1();
        __syncthreads();

        const uint32_t bufb = sb + (uint32_t)(c & 1) * STGSZ;
        #pragma unroll
        for (int ks = 0; ks < 4; ks++) {
            const int ksx = (ks + kofs) & 3;
            const uint32_t kb = (uint32_t)(ksx * 32);
            uint32_t bh[2][4], bp[2][4];
            #pragma unroll
            for (int np = 0; np < 2; np++) {
                const uint32_t bo = bBase + (uint32_t)(np * 16 * ROWB) + kb;
                ldsm_x4(bh[np][0], bh[np][1], bh[np][2], bh[np][3], bufb + BH_O + bo);
                ldsm_x4(bp[np][0], bp[np][1], bp[np][2], bp[np][3], bufb + BP_O + bo);
            }
            #pragma unroll
            for (int mt = 0; mt < 4; mt++) {
                uint32_t ah[4], ap[4];
                const uint32_t ao = aBase + (uint32_t)(mt * 16 * ROWB) + kb;
                ldsm_x4(ah[0], ah[1], ah[2], ah[3], bufb + AH_O + ao);
                ldsm_x4(ap[0], ap[1], ap[2], ap[3], bufb + AP_O + ao);
                #pragma unroll
                for (int nt = 0; nt < 4; nt++)
                    mma16816(accP[mt][nt], ah,
                             bh[nt >> 1][(nt & 1) * 2], bh[nt >> 1][(nt & 1) * 2 + 1]);
                #pragma unroll
                for (int nt = 0; nt < 4; nt++)
                    mma16816(accQ[mt][nt], ap,
                             bp[nt >> 1][(nt & 1) * 2], bp[nt >> 1][(nt & 1) * 2 + 1]);
            }
        }
        __syncthreads();
    }

    const int lr  = lane >> 2;
    const int lc2 = (lane & 3) * 2;
    #pragma unroll
    for (int mt = 0; mt < 4; mt++) {
        #pragma unroll
        for (int nt = 0; nt < 4; nt++) {
            const int gr = row0 + wm * 64 + mt * 16 + lr;
            const int gc = col0 + wn * 32 + nt * 8 + lc2;
            float vv[4];
            #pragma unroll
            for (int q = 0; q < 4; q++)
                vv[q] = fmaf(accQ[mt][nt][q] - accP[mt][nt][q], CINV_, accP[mt][nt][q]) * alpha;
            const long long o0 = coff + (long long)gr * ldc + gc;
            const long long o1 = coff + (long long)(gr + 8) * ldc + gc;
            if (Cf) {
                *reinterpret_cast<float2*>(Cf + o0) = make_float2(vv[0], vv[1]);
                *reinterpret_cast<float2*>(Cf + o1) = make_float2(vv[2], vv[3]);
            }
            if (Ch) {
                bf16 h0, p0, h1, p1, h2, p2, h3, p3;
                splitsc(vv[0], h0, p0); splitsc(vv[1], h1, p1);
                splitsc(vv[2], h2, p2); splitsc(vv[3], h3, p3);
                __nv_bfloat162 hv0; hv0.x = h0; hv0.y = h1;
                __nv_bfloat162 hv1; hv1.x = h2; hv1.y = h3;
                __nv_bfloat162 pv0; pv0.x = p0; pv0.y = p1;
                __nv_bfloat162 pv1; pv1.x = p2; pv1.y = p3;
                *reinterpret_cast<__nv_bfloat162*>(Ch + o0) = hv0;
                *reinterpret_cast<__nv_bfloat162*>(Ch + o1) = hv1;
                *reinterpret_cast<__nv_bfloat162*>(Cp + o0) = pv0;
                *reinterpret_cast<__nv_bfloat162*>(Cp + o1) = pv1;
            }
        }
    }
}

/* ---------------- split fp32 -> h/p bf16 ------------------------------------ */
__global__ void split_kernel(const float* __restrict__ x, bf16* __restrict__ h,
                             bf16* __restrict__ p, int n4)
{
    int idx = blockIdx.x * blockDim.x + threadIdx.x;
    if (idx >= n4) return;
    float4 v = reinterpret_cast<const float4*>(x)[idx];
    uint2 hh, pp;
    split4p(v, hh, pp);
    reinterpret_cast<uint2*>(h)[idx] = hh;
    reinterpret_cast<uint2*>(p)[idx] = pp;
}

/* ---------------- transpose [K,N] fp32 -> [N,K] h/p bf16 -------------------- */
__global__ void transpose_split_kernel(const float* __restrict__ in,
                                       bf16* __restrict__ outH, bf16* __restrict__ outP,
                                       int K, int N)
{
    __shared__ float t[32][33];
    int k0 = blockIdx.y * 32, n0 = blockIdx.x * 32;
    int x = threadIdx.x, y = threadIdx.y;
    #pragma unroll
    for (int i = 0; i < 32; i += 8) {
        int k = k0 + y + i, n = n0 + x;
        t[y + i][x] = (k < K && n < N) ? in[(long long)k * N + n] : 0.0f;
    }
    __syncthreads();
    #pragma unroll
    for (int i = 0; i < 32; i += 8) {
        int n = n0 + y + i, k = k0 + x;
        if (n < N && k < K) {
            bf16 hb, pb;
            splitsc(t[x][y + i], hb, pb);
            outH[(long long)n * K + k] = hb;
            outP[(long long)n * K + k] = pb;
        }
    }
}

/* ---------------- RMS norm -> h/p ------------------------------------------- */
__global__ __launch_bounds__(256) void rmsnorm_split_kernel(
    const float* __restrict__ x, const float* __restrict__ w,
    bf16* __restrict__ yh, bf16* __restrict__ yp, int n, int ldx, int ldy)
{
    int row = blockIdx.x;
    const float* xr = x + (long long)row * ldx;
    int tid = threadIdx.x;
    float ss = 0.0f;
    for (int i = tid; i < n; i += 256) { float v = xr[i]; ss += v * v; }
    __shared__ float red[8];
    #pragma unroll
    for (int o = 16; o; o >>= 1) ss += __shfl_xor_sync(0xffffffffu, ss, o);
    if ((tid & 31) == 0) red[tid >> 5] = ss;
    __syncthreads();
    if (tid < 32) {
        float v = (tid < 8) ? red[tid] : 0.0f;
        #pragma unroll
        for (int o = 4; o; o >>= 1) v += __shfl_xor_sync(0xffffffffu, v, o);
        if (tid == 0) red[0] = v;
    }
    __syncthreads();
    float inv = rsqrtf(red[0] / (float)n + 1e-6f);
    bf16* yhr = yh + (long long)row * ldy;
    bf16* ypr = yp + (long long)row * ldy;
    for (int i = tid; i < n; i += 256) {
        bf16 hb, pb;
        splitsc(w[i] * xr[i] * inv, hb, pb);
        yhr[i] = hb;
        ypr[i] = pb;
    }
}

/* ---------------- q rope -> qfull h/p ---------------------------------------- */
__global__ void qrope_split_kernel(const float* __restrict__ qf, const float* __restrict__ cs,
                                   const float* __restrict__ sn,
                                   bf16* __restrict__ oh, bf16* __restrict__ op)
{
    int idx = blockIdx.x * blockDim.x + threadIdx.x;
    const int total4 = B_ * H_ * S_ * (DQK_ / 4);
    if (idx >= total4) return;
    int d4 = idx % (DQK_ / 4);
    int t = idx / (DQK_ / 4);
    int s = t % S_; t /= S_;
    int h = t % H_;
    int b = t / H_;
    int d = d4 * 4;
    const float* src = qf + (((long long)(b * S_ + s)) * H_ + h) * DQK_;
    float4 val;
    if (d < DN_) {
        val = *reinterpret_cast<const float4*>(src + d);
    } else {
        int p = d - DN_;
        float4 x = *reinterpret_cast<const float4*>(src + DN_ + p);
        float4 other;
        if (p < DR_ / 2) {
            float4 o = *reinterpret_cast<const float4*>(src + DN_ + p + DR_ / 2);
            other = make_float4(-o.x, -o.y, -o.z, -o.w);
        } else {
            other = *reinterpret_cast<const float4*>(src + DN_ + p - DR_ / 2);
        }
        long long co = ((long long)b * S_ + s) * DR_ + p;
        float4 c = *reinterpret_cast<const float4*>(cs + co);
        float4 ss2 = *reinterpret_cast<const float4*>(sn + co);
        val.x = fmaf(x.x, c.x, other.x * ss2.x);
        val.y = fmaf(x.y, c.y, other.y * ss2.y);
        val.z = fmaf(x.z, c.z, other.z * ss2.z);
        val.w = fmaf(x.w, c.w, other.w * ss2.w);
    }
    uint2 hh, pp;
    split4p(val, hh, pp);
    reinterpret_cast<uint2*>(oh)[idx] = hh;
    reinterpret_cast<uint2*>(op)[idx] = pp;
}

/* k_pe rope; src rows have stride srcStride */
__global__ void krope_kernel(const float* __restrict__ src0, int srcStride,
                             const float* __restrict__ cs,
                             const float* __restrict__ sn, float* __restrict__ kpe)
{
    int idx = blockIdx.x * blockDim.x + threadIdx.x;
    if (idx >= B_ * S_ * (DR_ / 4)) return;
    int p4 = idx % (DR_ / 4);
    int bs = idx / (DR_ / 4);
    int p = p4 * 4;
    const float* src = src0 + (long long)bs * srcStride;
    float4 x = *reinterpret_cast<const float4*>(src + p);
    float4 other;
    if (p < DR_ / 2) {
        float4 o = *reinterpret_cast<const float4*>(src + p + DR_ / 2);
        other = make_float4(-o.x, -o.y, -o.z, -o.w);
    } else {
        other = *reinterpret_cast<const float4*>(src + p - DR_ / 2);
    }
    long long co = (long long)bs * DR_ + p;
    float4 c = *reinterpret_cast<const float4*>(cs + co);
    float4 ss2 = *reinterpret_cast<const float4*>(sn + co);
    float4 val;
    val.x = fmaf(x.x, c.x, other.x * ss2.x);
    val.y = fmaf(x.y, c.y, other.y * ss2.y);
    val.z = fmaf(x.z, c.z, other.z * ss2.z);
    val.w = fmaf(x.w, c.w, other.w * ss2.w);
    *reinterpret_cast<float4*>(kpe + co) = val;
}

__global__ void kbuild_split_kernel(const float* __restrict__ kvflat, const float* __restrict__ kpe,
                                    bf16* __restrict__ oh, bf16* __restrict__ op)
{
    int idx = blockIdx.x * blockDim.x + threadIdx.x;
    const int total4 = B_ * H_ * S_ * (DQK_ / 4);
    if (idx >= total4) return;
    int d4 = idx % (DQK_ / 4);
    int t = idx / (DQK_ / 4);
    int s = t % S_; t /= S_;
    int h = t % H_;
    int b = t / H_;
    int d = d4 * 4;
    float4 val;
    if (d < DN_)
        val = *reinterpret_cast<const float4*>(
            kvflat + (((long long)(b * S_ + s)) * H_ + h) * (DN_ + DV_) + d);
    else
        val = *reinterpret_cast<const float4*>(
            kpe + ((long long)b * S_ + s) * DR_ + (d - DN_));
    uint2 hh, pp;
    split4p(val, hh, pp);
    reinterpret_cast<uint2*>(oh)[idx] = hh;
    reinterpret_cast<uint2*>(op)[idx] = pp;
}

/* v transpose -> vT h/p [b,h,d,s] */
__global__ void vbuildT_split_kernel(const float* __restrict__ kvflat,
                                     bf16* __restrict__ oh, bf16* __restrict__ op)
{
    __shared__ float t[32][33];
    int bh = blockIdx.z;
    int b = bh >> 4, h = bh & 15;
    int s0 = blockIdx.x * 32, d0 = blockIdx.y * 32;
    int x = threadIdx.x, y = threadIdx.y;
    const float* src = kvflat + ((long long)b * S_ * H_ + h) * (DN_ + DV_) + DN_;
    #pragma unroll
    for (int i = 0; i < 32; i += 8) {
        int s = s0 + y + i, d = d0 + x;
        t[y + i][x] = src[(long long)s * (H_ * (DN_ + DV_)) + d];
    }
    __syncthreads();
    long long base = ((long long)bh * DV_) * S_;
    #pragma unroll
    for (int i = 0; i < 32; i += 8) {
        int d = d0 + y + i, s = s0 + x;
        bf16 hb, pb;
        splitsc(t[x][y + i], hb, pb);
        oh[base + (long long)d * S_ + s] = hb;
        op[base + (long long)d * S_ + s] = pb;
    }
}

/* -- causal softmax, vectorized -------------------------------------------- */
__global__ __launch_bounds__(256) void softmax_kernel(float* __restrict__ wts,
                                                      bf16* __restrict__ wh,
                                                      bf16* __restrict__ wp)
{
    long long row = blockIdx.x;
    int i = (int)(row % S_);
    float* r = wts + row * (long long)S_;
    bf16* rh = wh + row * (long long)S_;
    bf16* rp = wp + row * (long long)S_;
    const __nv_bfloat162* rh2 = reinterpret_cast<const __nv_bfloat162*>(rh);
    const __nv_bfloat162* rp2 = reinterpret_cast<const __nv_bfloat162*>(rp);
    int tid = threadIdx.x;
    int nvalid = i + 1;
    int nv2 = nvalid >> 1;
    bool odd = (nvalid & 1) != 0;
    int oddOwner = nv2 & 255;

    float e[8];
    float eodd = 0.0f;
    float mx = -1e30f;
    int cnt = 0;
    for (int j2 = tid; j2 < nv2; j2 += 256) {
        __nv_bfloat162 hv = rh2[j2];
        __nv_bfloat162 pv = rp2[j2];
        float h0 = __bfloat162float(hv.x), h1 = __bfloat162float(hv.y);
        float p0 = __bfloat162float(pv.x), p1 = __bfloat162float(pv.y);
        float e0 = fmaf(p0 - h0, CINV_, h0);
        float e1 = fmaf(p1 - h1, CINV_, h1);
        e[cnt++] = e0; e[cnt++] = e1;
        mx = fmaxf(mx, fmaxf(e0, e1));
    }
    if (odd && tid == oddOwner) {
        float hv = __bfloat162float(rh[nvalid - 1]);
        float pv = __bfloat162float(rp[nvalid - 1]);
        eodd = fmaf(pv - hv, CINV_, hv);
        mx = fmaxf(mx, eodd);
    }

    __shared__ float sm[8];
    #pragma unroll
    for (int o = 16; o; o >>= 1) mx = fmaxf(mx, __shfl_xor_sync(0xffffffffu, mx, o));
    if ((tid & 31) == 0) sm[tid >> 5] = mx;
    __syncthreads();
    if (tid < 32) {
        float v = (tid < 8) ? sm[tid] : -1e30f;
        #pragma unroll
        for (int o = 4; o; o >>= 1) v = fmaxf(v, __shfl_xor_sync(0xffffffffu, v, o));
        if (tid == 0) sm[0] = v;
    }
    __syncthreads();
    mx = sm[0];
    __syncthreads();

    float sum = 0.0f;
    cnt = 0;
    for (int j2 = tid; j2 < nv2; j2 += 256) {
        float e0 = fast_exp(e[cnt] - mx); e[cnt] = e0; cnt++;
        float e1 = fast_exp(e[cnt] - mx); e[cnt] = e1; cnt++;
        sum += e0 + e1;
    }
    if (odd && tid == oddOwner) { eodd = fast_exp(eodd - mx); sum += eodd; }
    #pragma unroll
    for (int o = 16; o; o >>= 1) sum += __shfl_xor_sync(0xffffffffu, sum, o);
    if ((tid & 31) == 0) sm[tid >> 5] = sum;
    __syncthreads();
    if (tid < 32) {
        float v = (tid < 8) ? sm[tid] : 0.0f;
        #pragma unroll
        for (int o = 4; o; o >>= 1) v += __shfl_xor_sync(0xffffffffu, v, o);
        if (tid == 0) sm[0] = v;
    }
    __syncthreads();
    float inv = 1.0f / sm[0];

    cnt = 0;
    for (int j2 = tid; j2 < nv2; j2 += 256) {
        float v0 = e[cnt++] * inv;
        float v1 = e[cnt++] * inv;
        reinterpret_cast<float2*>(r)[j2] = make_float2(v0, v1);
        bf16 h0, p0, h1, p1;
        splitsc(v0, h0, p0); splitsc(v1, h1, p1);
        __nv_bfloat162 hv; hv.x = h0; hv.y = h1;
        __nv_bfloat162 pv; pv.x = p0; pv.y = p1;
        reinterpret_cast<__nv_bfloat162*>(rh)[j2] = hv;
        reinterpret_cast<__nv_bfloat162*>(rp)[j2] = pv;
    }
    if (odd && tid == oddOwner) {
        float v = eodd * inv;
        r[nvalid - 1] = v;
        bf16 hb, pb;
        splitsc(v, hb, pb);
        rh[nvalid - 1] = hb;
        rp[nvalid - 1] = pb;
    }

    int bound = ((i >> 7) + 1) << 7;
    bf16 z = __float2bfloat16(0.0f);
    int zh0 = nvalid;
    if (zh0 & 1) {
        if (tid == 0 && zh0 < bound) { rh[zh0] = z; rp[zh0] = z; }
        zh0++;
    }
    __nv_bfloat162 z2; z2.x = z; z2.y = z;
    for (int j2 = (zh0 >> 1) + tid; j2 < (bound >> 1); j2 += 256) {
        reinterpret_cast<__nv_bfloat162*>(rh)[j2] = z2;
        reinterpret_cast<__nv_bfloat162*>(rp)[j2] = z2;
    }
    int z4s = (nvalid + 3) & ~3;
    for (int j = nvalid + tid; j < z4s && j < S_; j += 256) r[j] = 0.0f;
    float4 zf4 = make_float4(0.f, 0.f, 0.f, 0.f);
    for (int j4 = (z4s >> 2) + tid; j4 < (S_ >> 2); j4 += 256)
        reinterpret_cast<float4*>(r)[j4] = zf4;
}

/* ---------------- host ------------------------------------------------------ */
static inline void mma_gemm_s(cudaStream_t st,
                              const bf16* Ah, const bf16* Ap, const bf16* Bh, const bf16* Bp,
                              float* Cf, bf16* Ch, bf16* Cp,
                              int M, int N, int K, int lda, int ldb, int ldc,
                              long long sA, long long sB,
                              int zdiv, long long csOut, long long csIn,
                              float alpha, int causalSkip, int causalK, int batch)
{
    dim3 grid((N + 63) / 64, (M + 127) / 128, batch);
    mma_gemm11_kernel<<<grid, 128, GEMM_SMEM, st>>>(Ah, Ap, Bh, Bp, Cf, Ch, Cp,
                                                    M, N, K, lda, ldb, ldc,
                                                    sA, sB, zdiv, csOut, csIn,
                                                    alpha, causalSkip, causalK);
}

extern "C" void kernel_launch(void* const* d_in, const int* in_sizes, int n_in,
                              void* d_out, int out_size)
{
    const float* hs      = (const float*)d_in[0];
    const float* cs      = (const float*)d_in[1];
    const float* sn      = (const float*)d_in[2];
    const float* q_a_w   = (const float*)d_in[4];
    const float* q_a_ln  = (const float*)d_in[5];
    const float* q_b_w   = (const float*)d_in[6];
    const float* kv_a_w  = (const float*)d_in[7];
    const float* kv_a_ln = (const float*)d_in[8];
    const float* kv_b_w  = (const float*)d_in[9];
    const float* o_w     = (const float*)d_in[10];

    float* out = (float*)d_out;
    float* wts = out + (long long)B_ * S_ * HID_;

    static bool init_done = false;
    static cudaStream_t s1, s2;
    static cudaEvent_t evA, evW, evG1, evKV, evQ, evAT2;
    if (!init_done) {
        cudaFuncSetAttribute(mma_gemm11_kernel, cudaFuncAttributeMaxDynamicSharedMemorySize, GEMM_SMEM);
        cudaStreamCreateWithFlags(&s1, cudaStreamNonBlocking);
        cudaStreamCreateWithFlags(&s2, cudaStreamNonBlocking);
        cudaEventCreateWithFlags(&evA,   cudaEventDisableTiming);
        cudaEventCreateWithFlags(&evW,   cudaEventDisableTiming);
        cudaEventCreateWithFlags(&evG1,  cudaEventDisableTiming);
        cudaEventCreateWithFlags(&evKV,  cudaEventDisableTiming);
        cudaEventCreateWithFlags(&evQ,   cudaEventDisableTiming);
        cudaEventCreateWithFlags(&evAT2, cudaEventDisableTiming);
        init_done = true;
    }
    cudaStream_t s0 = 0;

#define GETSYM(p, s) cudaGetSymbolAddress((void**)&p, s)
    bf16 *hsh, *hsp, *qlnh, *qlnp, *qfh, *qfp, *kch, *kcp, *kfh, *kfp, *vth, *vtp;
    bf16 *whh, *whp, *omh, *omp;
    bf16 *wqkvh, *wqkvp, *wqbh, *wqbp, *wkbh, *wkbp, *woh, *wop;
    float *qkvlat, *qflat, *kpe, *kvflat;
    GETSYM(hsh, g_hs_h);    GETSYM(hsp, g_hs_p);
    GETSYM(qkvlat, g_qkvlat);
    GETSYM(qlnh, g_qlatn_h);  GETSYM(qlnp, g_qlatn_p);
    GETSYM(qflat, g_qflat); GETSYM(qfh, g_qfull_h);   GETSYM(qfp, g_qfull_p);
    GETSYM(kch, g_kc_h);    GETSYM(kcp, g_kc_p);
    GETSYM(kpe, g_kpe);     GETSYM(kvflat, g_kvflat);
    GETSYM(kfh, g_kfull_h); GETSYM(kfp, g_kfull_p);
    GETSYM(vth, g_vT_h);    GETSYM(vtp, g_vT_p);
    GETSYM(whh, g_w_h);     GETSYM(whp, g_w_p);
    GETSYM(omh, g_omid_h);  GETSYM(omp, g_omid_p);
    GETSYM(wqkvh, g_wqkvT_h); GETSYM(wqkvp, g_wqkvT_p);
    GETSYM(wqbh, g_wqbT_h); GETSYM(wqbp, g_wqbT_p);
    GETSYM(wkbh, g_wkvbT_h); GETSYM(wkbp, g_wkvbT_p);
    GETSYM(woh, g_woT_h);   GETSYM(wop, g_woT_p);
#undef GETSYM

    dim3 tb(32, 8);

    /* half-offsets (half = one batch b; 16 heads) */
    const long long hqk = 16LL * S_ * DQK_;      /* qfull/kfull per-half elems */
    const long long hw  = 16LL * S_ * S_;        /* weights per-half elems     */
    const long long hv  = 16LL * DV_ * S_;       /* vT per-half elems          */
    const long long hom = (long long)S_ * H_ * DV_; /* omid per-half elems     */

    /* fork root */
    cudaEventRecord(evA, s0);

    /* --- s0: launches 0..3 (index 3 = fused GEMM, profiled) --- */
    transpose_split_kernel<<<dim3(QLORA_ / 32, HID_ / 32), tb, 0, s0>>>(q_a_w, wqkvh, wqkvp, HID_, QLORA_);
    transpose_split_kernel<<<dim3((KVLORA_ + DR_) / 32, HID_ / 32), tb, 0, s0>>>(
        kv_a_w, wqkvh + (long long)QLORA_ * HID_, wqkvp + (long long)QLORA_ * HID_,
        HID_, KVLORA_ + DR_);
    split_kernel<<<(NTOK_ * HID_ / 4 + 255) / 256, 256, 0, s0>>>(hs, hsh, hsp, NTOK_ * HID_ / 4);
    mma_gemm_s(s0, hsh, hsp, wqkvh, wqkvp, qkvlat, 0, 0,
               NTOK_, QKVN_, HID_, HID_, HID_, QKVN_,
               0, 0, 1, 0, 0, 1.0f, 0, 0, 1);
    cudaEventRecord(evG1, s0);

    /* --- s1: independent weight transposes --- */
    cudaStreamWaitEvent(s1, evA, 0);
    transpose_split_kernel<<<dim3(H_ * DQK_ / 32, QLORA_ / 32), tb, 0, s1>>>(q_b_w, wqbh, wqbp, QLORA_, H_ * DQK_);
    transpose_split_kernel<<<dim3(H_ * (DN_ + DV_) / 32, KVLORA_ / 32), tb, 0, s1>>>(kv_b_w, wkbh, wkbp, KVLORA_, H_ * (DN_ + DV_));
    transpose_split_kernel<<<dim3(HID_ / 32, (H_ * DV_) / 32), tb, 0, s1>>>(o_w, woh, wop, H_ * DV_, HID_);
    cudaEventRecord(evW, s1);

    /* --- s2: kv track --- */
    cudaStreamWaitEvent(s2, evG1, 0);
    cudaStreamWaitEvent(s2, evW, 0);
    rmsnorm_split_kernel<<<NTOK_, 256, 0, s2>>>(qkvlat + QLORA_, kv_a_ln, kch, kcp, KVLORA_, QKVN_, KVLORA_);
    krope_kernel<<<(B_ * S_ * (DR_ / 4) + 255) / 256, 256, 0, s2>>>(
        qkvlat + QLORA_ + KVLORA_, QKVN_, cs, sn, kpe);
    mma_gemm_s(s2, kch, kcp, wkbh, wkbp, kvflat, 0, 0,
               NTOK_, H_ * (DN_ + DV_), KVLORA_, KVLORA_, KVLORA_, H_ * (DN_ + DV_),
               0, 0, 1, 0, 0, 1.0f, 0, 0, 1);
    kbuild_split_kernel<<<(B_ * H_ * S_ * (DQK_ / 4) + 255) / 256, 256, 0, s2>>>(kvflat, kpe, kfh, kfp);
    vbuildT_split_kernel<<<dim3(S_ / 32, DV_ / 32, B_ * H_), tb, 0, s2>>>(kvflat, vth, vtp);
    cudaEventRecord(evKV, s2);

    /* --- s0: q track --- */
    rmsnorm_split_kernel<<<NTOK_, 256, 0, s0>>>(qkvlat, q_a_ln, qlnh, qlnp, QLORA_, QKVN_, QLORA_);
    cudaStreamWaitEvent(s0, evW, 0);
    mma_gemm_s(s0, qlnh, qlnp, wqbh, wqbp, qflat, 0, 0,
               NTOK_, H_ * DQK_, QLORA_, QLORA_, QLORA_, H_ * DQK_,
               0, 0, 1, 0, 0, 1.0f, 0, 0, 1);
    qrope_split_kernel<<<(B_ * H_ * S_ * (DQK_ / 4) + 255) / 256, 256, 0, s0>>>(qflat, cs, sn, qfh, qfp);
    cudaEventRecord(evQ, s0);

    /* --- attention: two batch halves pipelined on s0 / s2 --- */
    /* half 1 (bh 0..15) on s0 */
    cudaStreamWaitEvent(s0, evKV, 0);
    mma_gemm_s(s0, qfh, qfp, kfh, kfp, 0, whh, whp,
               S_, S_, DQK_, DQK_, DQK_, S_,
               (long long)S_ * DQK_, (long long)S_ * DQK_,
               1, (long long)S_ * S_, 0,
               SCALING_, 1, 0, 16);
    softmax_kernel<<<16 * S_, 256, 0, s0>>>(wts, whh, whp);
    mma_gemm_s(s0, whh, whp, vth, vtp, 0, omh, omp,
               S_, DV_, S_, S_, S_, H_ * DV_,
               (long long)S_ * S_, (long long)DV_ * S_,
               H_, hom, (long long)DV_,
               1.0f, 0, 1, 16);

    /* half 2 (bh 16..31) on s2 */
    cudaStreamWaitEvent(s2, evQ, 0);
    mma_gemm_s(s2, qfh + hqk, qfp + hqk, kfh + hqk, kfp + hqk,
               0, whh + hw, whp + hw,
               S_, S_, DQK_, DQK_, DQK_, S_,
               (long long)S_ * DQK_, (long long)S_ * DQK_,
               1, (long long)S_ * S_, 0,
               SCALING_, 1, 0, 16);
    softmax_kernel<<<16 * S_, 256, 0, s2>>>(wts + hw, whh + hw, whp + hw);
    mma_gemm_s(s2, whh + hw, whp + hw, vth + hv, vtp + hv,
               0, omh + hom, omp + hom,
               S_, DV_, S_, S_, S_, H_ * DV_,
               (long long)S_ * S_, (long long)DV_ * S_,
               H_, hom, (long long)DV_,
               1.0f, 0, 1, 16);
    cudaEventRecord(evAT2, s2);

    /* join, then o_proj */
    cudaStreamWaitEvent(s0, evAT2, 0);
    mma_gemm_s(s0, omh, omp, woh, wop, out, 0, 0,
               NTOK_, HID_, H_ * DV_, H_ * DV_, H_ * DV_, HID_,
               0, 0, 1, 0, 0, 1.0f, 0, 0, 1);
}